// round 14
// baseline (speedup 1.0000x reference)
#include <cuda_runtime.h>
#include <cuda_fp16.h>
#include <math.h>
#include <stdint.h>

static const int BB   = 8;
static const int NN   = 1024;
static const int DD   = 512;
static const int HEADS= 8;
static const int DFF  = 2048;
static const int ROWS = BB * NN;        // 8192
#define EPSF 1e-5f
#define LAMBDA_INIT 0.2f

// ---------------- scratch ---------------------------------------------------
__device__ float  g_lam[1];
__device__ __half g_xnh[ROWS * DD];
__device__ __half g_qh [ROWS * DD];
__device__ __half g_kh [ROWS * DD];
__device__ __half g_vh [ROWS * DD];
__device__ __half g_aoh[ROWS * DD];
__device__ float  g_a  [ROWS * DD];
__device__ float  g_h  [ROWS * DD];
__device__ __half g_zh [ROWS * DD];
__device__ __half g_z1h[ROWS * DFF];
__device__ __half g_z2h[ROWS * DFF];
__device__ __half g_Wqh[DD * DD];
__device__ __half g_Wkh[DD * DD];
__device__ __half g_Wvh[DD * DD];
__device__ __half g_Woh[DD * DD];
__device__ __half g_W1h[DFF * DD];
__device__ __half g_W2h[DD * DFF];

// ---------------- helpers ----------------------------------------------------
__device__ __forceinline__ uint32_t smem_u32(const void* p) {
    uint32_t a;
    asm("{ .reg .u64 t; cvta.to.shared.u64 t, %1; cvt.u32.u64 %0, t; }" : "=r"(a) : "l"(p));
    return a;
}
__device__ __forceinline__ __half2 u2h(uint32_t u) { return *(__half2*)&u; }
__device__ __forceinline__ uint32_t ex2h2(float a, float b) {
    __half2 t = __floats2half2_rn(a, b);
    uint32_t u = *(uint32_t*)&t, r;
    asm("ex2.approx.f16x2 %0, %1;" : "=r"(r) : "r"(u));
    return r;
}
#define CPA16(dst, src) asm volatile("cp.async.cg.shared.global [%0], [%1], 16;" :: "r"(dst), "l"(src) : "memory")
#define CP_COMMIT()     asm volatile("cp.async.commit_group;" ::: "memory")
#define CP_WAIT1()      asm volatile("cp.async.wait_group 1;" ::: "memory")
#define LDSM_X4(r0,r1,r2,r3,addr) \
    asm volatile("ldmatrix.sync.aligned.m8n8.x4.shared.b16 {%0,%1,%2,%3}, [%4];" \
                 : "=r"(r0),"=r"(r1),"=r"(r2),"=r"(r3) : "r"(addr))
#define LDSM_X4T(r0,r1,r2,r3,addr) \
    asm volatile("ldmatrix.sync.aligned.m8n8.x4.trans.shared.b16 {%0,%1,%2,%3}, [%4];" \
                 : "=r"(r0),"=r"(r1),"=r"(r2),"=r"(r3) : "r"(addr))
#define MMA_F16(c0,c1,c2,c3,a0,a1,a2,a3,b0,b1) \
    asm volatile("mma.sync.aligned.m16n8k16.row.col.f32.f16.f16.f32 " \
                 "{%0,%1,%2,%3}, {%4,%5,%6,%7}, {%8,%9}, {%0,%1,%2,%3};" \
                 : "+f"(c0),"+f"(c1),"+f"(c2),"+f"(c3) \
                 : "r"(a0),"r"(a1),"r"(a2),"r"(a3),"r"(b0),"r"(b1))

// ---------------- weights fp32 -> fp16 (+ lambda in block 0) -----------------
__global__ void cvt_weights(const float* __restrict__ Wq, const float* __restrict__ Wk,
                            const float* __restrict__ Wv, const float* __restrict__ Wo,
                            const float* __restrict__ W1, const float* __restrict__ W2,
                            const float* __restrict__ lq1, const float* __restrict__ lk1,
                            const float* __restrict__ lq2, const float* __restrict__ lk2) {
    if (blockIdx.x == 0 && threadIdx.x < 32) {
        int t = threadIdx.x;
        float a = lq1[t] * lk1[t];
        float b = lq2[t] * lk2[t];
        #pragma unroll
        for (int o = 16; o; o >>= 1) {
            a += __shfl_xor_sync(0xffffffffu, a, o);
            b += __shfl_xor_sync(0xffffffffu, b, o);
        }
        if (t == 0) g_lam[0] = expf(a) - expf(b) + LAMBDA_INIT;
    }
    int i = blockIdx.x * 256 + threadIdx.x;
    if (i < DD * DD) {
        g_Wqh[i] = __float2half_rn(Wq[i]);
        g_Wkh[i] = __float2half_rn(Wk[i]);
        g_Wvh[i] = __float2half_rn(Wv[i]);
        g_Woh[i] = __float2half_rn(Wo[i]);
    }
    if (i < DFF * DD) {
        g_W1h[i] = __float2half_rn(W1[i]);
        g_W2h[i] = __float2half_rn(W2[i]);
    }
}

// ---------------- LayerNorm; flags: bit0 = half out, bit1 = half in ---------
__global__ void ln_kernel(const void* __restrict__ Xv, const float* __restrict__ w,
                          const float* __restrict__ bvec, const float* __restrict__ res,
                          void* __restrict__ Y, int dim, int flags) {
    int row = blockIdx.x;
    int t   = threadIdx.x;
    int cnt = dim >> 8;
    float xi[8];
    float s = 0.f;
    if (flags & 2) {
        const __half* xr = (const __half*)Xv + (size_t)row * dim;
        for (int i = 0; i < cnt; i++) { xi[i] = __half2float(xr[t + 256 * i]); s += xi[i]; }
    } else {
        const float* xr = (const float*)Xv + (size_t)row * dim;
        for (int i = 0; i < cnt; i++) { xi[i] = xr[t + 256 * i]; s += xi[i]; }
    }

    __shared__ float red[8];
    #pragma unroll
    for (int o = 16; o; o >>= 1) s += __shfl_xor_sync(0xffffffffu, s, o);
    if ((t & 31) == 0) red[t >> 5] = s;
    __syncthreads();
    float tot = 0.f;
    #pragma unroll
    for (int i = 0; i < 8; i++) tot += red[i];
    float mu = tot / (float)dim;

    float v = 0.f;
    for (int i = 0; i < cnt; i++) { float d = xi[i] - mu; v += d * d; }
    __syncthreads();
    #pragma unroll
    for (int o = 16; o; o >>= 1) v += __shfl_xor_sync(0xffffffffu, v, o);
    if ((t & 31) == 0) red[t >> 5] = v;
    __syncthreads();
    float vt = 0.f;
    #pragma unroll
    for (int i = 0; i < 8; i++) vt += red[i];
    float rstd = rsqrtf(vt / (float)dim + EPSF);

    const float* rr = res ? res + (size_t)row * dim : nullptr;
    for (int i = 0; i < cnt; i++) {
        int c = t + 256 * i;
        float y = (xi[i] - mu) * rstd * w[c] + bvec[c];
        if (rr) y += rr[c];
        if (flags & 1) ((__half*)Y)[(size_t)row * dim + c] = __float2half_rn(y);
        else           ((float*)Y)[(size_t)row * dim + c] = y;
    }
}

// ---------------- fused: h = LN(a)+x (fp32), zh = LN(h) (fp16) --------------
__global__ void ln_fuse2(const float* __restrict__ A, const float* __restrict__ x,
                         const float* __restrict__ n2w, const float* __restrict__ n2b,
                         const float* __restrict__ m1w, const float* __restrict__ m1b,
                         float* __restrict__ H, __half* __restrict__ Z) {
    int row = blockIdx.x;
    int t   = threadIdx.x;
    const float* ar = A + (size_t)row * DD;
    float a0 = ar[t], a1 = ar[t + 256];

    __shared__ float red[8];
    float s = a0 + a1;
    #pragma unroll
    for (int o = 16; o; o >>= 1) s += __shfl_xor_sync(0xffffffffu, s, o);
    if ((t & 31) == 0) red[t >> 5] = s;
    __syncthreads();
    float tot = 0.f;
    #pragma unroll
    for (int i = 0; i < 8; i++) tot += red[i];
    float mu = tot * (1.0f / DD);
    float d0 = a0 - mu, d1 = a1 - mu;
    float v = d0 * d0 + d1 * d1;
    __syncthreads();
    #pragma unroll
    for (int o = 16; o; o >>= 1) v += __shfl_xor_sync(0xffffffffu, v, o);
    if ((t & 31) == 0) red[t >> 5] = v;
    __syncthreads();
    float vt = 0.f;
    #pragma unroll
    for (int i = 0; i < 8; i++) vt += red[i];
    float rstd = rsqrtf(vt * (1.0f / DD) + EPSF);

    int c0 = t, c1 = t + 256;
    float h0 = d0 * rstd * n2w[c0] + n2b[c0] + x[(size_t)row * DD + c0];
    float h1 = d1 * rstd * n2w[c1] + n2b[c1] + x[(size_t)row * DD + c1];
    H[(size_t)row * DD + c0] = h0;
    H[(size_t)row * DD + c1] = h1;

    float s2 = h0 + h1;
    __syncthreads();
    #pragma unroll
    for (int o = 16; o; o >>= 1) s2 += __shfl_xor_sync(0xffffffffu, s2, o);
    if ((t & 31) == 0) red[t >> 5] = s2;
    __syncthreads();
    float tot2 = 0.f;
    #pragma unroll
    for (int i = 0; i < 8; i++) tot2 += red[i];
    float mu2 = tot2 * (1.0f / DD);
    float e0 = h0 - mu2, e1 = h1 - mu2;
    float v2 = e0 * e0 + e1 * e1;
    __syncthreads();
    #pragma unroll
    for (int o = 16; o; o >>= 1) v2 += __shfl_xor_sync(0xffffffffu, v2, o);
    if ((t & 31) == 0) red[t >> 5] = v2;
    __syncthreads();
    float vt2 = 0.f;
    #pragma unroll
    for (int i = 0; i < 8; i++) vt2 += red[i];
    float rstd2 = rsqrtf(vt2 * (1.0f / DD) + EPSF);

    Z[(size_t)row * DD + c0] = __float2half_rn(e0 * rstd2 * m1w[c0] + m1b[c0]);
    Z[(size_t)row * DD + c1] = __float2half_rn(e1 * rstd2 * m1w[c1] + m1b[c1]);
}

// ---------------- fp16 GEMM (128x128, 3-stage, 2 CTA/SM, paired-B x4) --------
// epi: 0 f32, 2 gelu+bias f32, 3 bias+res f32, 4 half*oscale, 5 gelu+bias half
#define HST 72
#define STG_H (128 * HST)
#define GEMM_SMEM (3 * 2 * STG_H * 2)

__device__ __forceinline__ void gemm_h_issue(
        const __half* A, const __half* W, int K, int bm, int bn,
        uint32_t sb, int t, int ch, int s) {
    const __half* Ap = A + (size_t)bm * K + ch * 64;
    const __half* Wp = W + (size_t)bn * K + ch * 64;
    uint32_t ab = sb + (uint32_t)((s * 2 + 0) * STG_H) * 2;
    uint32_t wb = sb + (uint32_t)((s * 2 + 1) * STG_H) * 2;
    #pragma unroll
    for (int i = 0; i < 4; i++) {
        int f = i * 256 + t;
        int row = f >> 3, c = f & 7;
        CPA16(ab + (uint32_t)(row * HST + c * 8) * 2, Ap + (size_t)row * K + c * 8);
        CPA16(wb + (uint32_t)(row * HST + c * 8) * 2, Wp + (size_t)row * K + c * 8);
    }
}

__device__ __forceinline__ void gemm_h_core(
        const __half* __restrict__ A, const __half* __restrict__ W,
        const float* __restrict__ bias, const float* __restrict__ res,
        void* __restrict__ Cout, int Nn, int K, int epi, float oscale,
        int bm, int bn, uint32_t sb, int t) {
    int lane = t & 31, wid = t >> 5;
    int warp_m = (wid & 1) * 64;
    int warp_n = (wid >> 1) * 32;
    int ar = lane & 15;
    int ak = (lane >> 4) * 8;
    int brr = (lane & 7) + ((lane >> 4) << 3);
    int bkk = ((lane >> 3) & 1) * 8;

    float c[16][4];
    #pragma unroll
    for (int i = 0; i < 16; i++)
        #pragma unroll
        for (int j = 0; j < 4; j++) c[i][j] = 0.f;

    const int nc = K >> 6;
    gemm_h_issue(A, W, K, bm, bn, sb, t, 0, 0); CP_COMMIT();
    gemm_h_issue(A, W, K, bm, bn, sb, t, 1, 1); CP_COMMIT();

    for (int ch = 0; ch < nc; ch++) {
        CP_WAIT1();
        __syncthreads();
        if (ch + 2 < nc) gemm_h_issue(A, W, K, bm, bn, sb, t, ch + 2, (ch + 2) % 3);
        CP_COMMIT();

        int s = ch % 3;
        uint32_t ab = sb + (uint32_t)((s * 2 + 0) * STG_H) * 2;
        uint32_t wb = sb + (uint32_t)((s * 2 + 1) * STG_H) * 2;
        #pragma unroll
        for (int ks = 0; ks < 4; ks++) {
            int k0 = ks * 16;
            uint32_t af[4][4];
            #pragma unroll
            for (int mt = 0; mt < 4; mt++) {
                uint32_t addr = ab + (uint32_t)((warp_m + mt * 16 + ar) * HST + k0 + ak) * 2;
                LDSM_X4(af[mt][0], af[mt][1], af[mt][2], af[mt][3], addr);
            }
            uint32_t bf[4][2];
            #pragma unroll
            for (int np = 0; np < 2; np++) {
                uint32_t addr = wb + (uint32_t)((warp_n + np * 16 + brr) * HST + k0 + bkk) * 2;
                LDSM_X4(bf[np*2][0], bf[np*2][1], bf[np*2+1][0], bf[np*2+1][1], addr);
            }
            #pragma unroll
            for (int mt = 0; mt < 4; mt++)
                #pragma unroll
                for (int nt = 0; nt < 4; nt++)
                    MMA_F16(c[mt*4+nt][0], c[mt*4+nt][1], c[mt*4+nt][2], c[mt*4+nt][3],
                            af[mt][0], af[mt][1], af[mt][2], af[mt][3],
                            bf[nt][0], bf[nt][1]);
        }
    }

    int qrow = lane >> 2;
    int qcol = (lane & 3) * 2;
    #pragma unroll
    for (int mt = 0; mt < 4; mt++) {
        #pragma unroll
        for (int nt = 0; nt < 4; nt++) {
            int idx = mt * 4 + nt;
            int col = bn + warp_n + nt * 8 + qcol;
            #pragma unroll
            for (int hf = 0; hf < 2; hf++) {
                int row = bm + warp_m + mt * 16 + qrow + hf * 8;
                float v0 = c[idx][hf * 2 + 0];
                float v1 = c[idx][hf * 2 + 1];
                if (epi == 2 || epi == 3 || epi == 5) { v0 += bias[col]; v1 += bias[col + 1]; }
                if (epi == 2 || epi == 5) {
                    v0 = 0.5f * v0 * (1.0f + erff(v0 * 0.70710678118654752f));
                    v1 = 0.5f * v1 * (1.0f + erff(v1 * 0.70710678118654752f));
                }
                if (epi == 3) {
                    const float* rp = res + (size_t)row * Nn + col;
                    v0 += rp[0]; v1 += rp[1];
                }
                if (epi == 4 || epi == 5) {
                    *(__half2*)((__half*)Cout + (size_t)row * Nn + col) =
                        __floats2half2_rn(v0 * oscale, v1 * oscale);
                } else {
                    float2 o; o.x = v0; o.y = v1;
                    *(float2*)((float*)Cout + (size_t)row * Nn + col) = o;
                }
            }
        }
    }
}

__global__ __launch_bounds__(256, 2) void gemm_h(
        const __half* __restrict__ A, const __half* __restrict__ W,
        const float* __restrict__ bias, const float* __restrict__ res,
        void* __restrict__ Cout, int Nn, int K, int epi) {
    extern __shared__ __half smh[];
    gemm_h_core(A, W, bias, res, Cout, Nn, K, epi, 1.0f,
                blockIdx.y * 128, blockIdx.x * 128, smem_u32(smh), threadIdx.x);
}

__global__ __launch_bounds__(256, 2) void qkv_h(const __half* __restrict__ A) {
    extern __shared__ __half smh[];
    int sel = blockIdx.x >> 2;
    const __half* W = (sel == 0) ? g_Wqh : (sel == 1) ? g_Wkh : g_Wvh;
    __half* C       = (sel == 0) ? g_qh  : (sel == 1) ? g_kh  : g_vh;
    float sc = (sel == 0) ? (0.17677669529663687f * 1.4426950408889634f) : 1.0f;
    gemm_h_core(A, W, nullptr, nullptr, C, DD, DD, 4, sc,
                blockIdx.y * 128, (blockIdx.x & 3) * 128, smem_u32(smh), threadIdx.x);
}

// ---------------- fp16 differential attention: 64q CTAs ----------------------
// grid (N/64, HEADS, B) = 1024 CTAs, 256 threads (8 warps: 2M x 4 key-groups).
// Each warp: 32 q rows x 16 keys/tile; PV contracts its keys over full d=64.
// 4 partial O combined at end via 3 smem regions.
#define AH 72
#define Q_OFF  0
#define K_OFF  (64 * AH)                     // Q: 64 rows
#define V_OFF  (K_OFF + 3 * 64 * AH)
#define ATT_H  (V_OFF + 3 * 64 * AH)
#define OBUF_B (ATT_H * 2)                   // 3 regions x 64x64 f32
#define SSUM_B (OBUF_B + 3 * 64 * 64 * 4)
#define ATTN_SMEM (SSUM_B + 2 * 64 * 4)

__device__ __forceinline__ void attn_issue_kv(const __half* Kg, const __half* Vg,
                                              uint32_t sb, int t, int kt) {
    int m0 = kt * 64;
    int bufo = (kt % 3) * 64 * AH;
    #pragma unroll
    for (int i = 0; i < 2; i++) {
        int f = i * 256 + t;
        int row = f >> 3, c = f & 7;
        CPA16(sb + (uint32_t)(K_OFF + bufo + row * AH + c * 8) * 2, Kg + (size_t)(m0 + row) * DD + c * 8);
        CPA16(sb + (uint32_t)(V_OFF + bufo + row * AH + c * 8) * 2, Vg + (size_t)(m0 + row) * DD + c * 8);
    }
}

__global__ __launch_bounds__(256, 1) void attn_h(const float* __restrict__ subw,
                                                 __half* __restrict__ O) {
    extern __shared__ __half smh[];
    uint32_t sb = smem_u32(smh);
    float* obuf  = (float*)((char*)smh + OBUF_B);
    float* ssum1 = (float*)((char*)smh + SSUM_B);
    float* ssum2 = ssum1 + 64;

    int n0 = blockIdx.x * 64;
    int h  = blockIdx.y;
    int b  = blockIdx.z;
    int t  = threadIdx.x;
    int lane = t & 31, wid = t >> 5;
    size_t base = (size_t)b * NN * DD;
    const __half* Qg = g_qh + base + h * 64;
    const __half* Kg = g_kh + base + h * 64;
    const __half* Vg = g_vh + base + h * 64;

    int wm  = (wid & 1) * 32;      // 2 M-groups of 32 q rows
    int wgn = (wid >> 1);          // 4 key-groups of 16 keys
    int ar = lane & 15;
    int ak = (lane >> 4) * 8;
    int br = lane & 7;
    int bk = ((lane >> 3) & 1) * 8;
    int brr = (lane & 7) + ((lane >> 4) << 3);
    int bkk = ((lane >> 3) & 1) * 8;
    int vd  = (lane >> 4) << 3;
    int qrow = lane >> 2;
    int qcol = (lane & 3) * 2;

    // prologue: Q (64 rows) + KV0, KV1
    #pragma unroll
    for (int i = 0; i < 2; i++) {
        int f = i * 256 + t;
        int q = f >> 3, c = f & 7;
        CPA16(sb + (uint32_t)(Q_OFF + q * AH + c * 8) * 2, Qg + (size_t)(n0 + q) * DD + c * 8);
    }
    attn_issue_kv(Kg, Vg, sb, t, 0);
    CP_COMMIT();
    attn_issue_kv(Kg, Vg, sb, t, 1);
    CP_COMMIT();

    if (t < 64) { ssum1[t] = 0.f; ssum2[t] = 0.f; }

    float o1[2][8][4], o2[2][8][4];
    #pragma unroll
    for (int mt = 0; mt < 2; mt++)
        #pragma unroll
        for (int nt = 0; nt < 8; nt++)
            #pragma unroll
            for (int i = 0; i < 4; i++) { o1[mt][nt][i] = 0.f; o2[mt][nt][i] = 0.f; }
    float sp1[2][2] = {{0.f,0.f},{0.f,0.f}};
    float sp2[2][2] = {{0.f,0.f},{0.f,0.f}};

    uint32_t qb = sb + (uint32_t)Q_OFF * 2;
    uint32_t qf[2][2][2][4];   // [sub][ks][mt][frag]

    for (int kt = 0; kt < 16; kt++) {
        CP_WAIT1();
        __syncthreads();
        if (kt == 0) {
            #pragma unroll
            for (int sub = 0; sub < 2; sub++)
                #pragma unroll
                for (int ks = 0; ks < 2; ks++)
                    #pragma unroll
                    for (int mt = 0; mt < 2; mt++) {
                        uint32_t addr = qb + (uint32_t)((wm + mt * 16 + ar) * AH + sub * 32 + ks * 16 + ak) * 2;
                        LDSM_X4(qf[sub][ks][mt][0], qf[sub][ks][mt][1],
                                qf[sub][ks][mt][2], qf[sub][ks][mt][3], addr);
                    }
        }
        if (kt + 2 < 16) attn_issue_kv(Kg, Vg, sb, t, kt + 2);
        CP_COMMIT();

        uint32_t kb = sb + (uint32_t)(K_OFF + (kt % 3) * 64 * AH) * 2;
        uint32_t vb = sb + (uint32_t)(V_OFF + (kt % 3) * 64 * AH) * 2;
        int key0 = wgn * 16;

        // S phase: warp's 16 keys (2 n8 tiles), both sub-heads
        float c1[2][2][4], c2[2][2][4];
        #pragma unroll
        for (int mt = 0; mt < 2; mt++)
            #pragma unroll
            for (int nt = 0; nt < 2; nt++)
                #pragma unroll
                for (int i = 0; i < 4; i++) { c1[mt][nt][i] = 0.f; c2[mt][nt][i] = 0.f; }

        #pragma unroll
        for (int sub = 0; sub < 2; sub++) {
            #pragma unroll
            for (int ks = 0; ks < 2; ks++) {
                int k0 = sub * 32 + ks * 16;
                uint32_t bf[2][2];
                {
                    uint32_t addr = kb + (uint32_t)((key0 + brr) * AH + k0 + bkk) * 2;
                    LDSM_X4(bf[0][0], bf[0][1], bf[1][0], bf[1][1], addr);
                }
                #pragma unroll
                for (int mt = 0; mt < 2; mt++)
                    #pragma unroll
                    for (int nt = 0; nt < 2; nt++) {
                        if (sub == 0)
                            MMA_F16(c1[mt][nt][0], c1[mt][nt][1], c1[mt][nt][2], c1[mt][nt][3],
                                    qf[0][ks][mt][0], qf[0][ks][mt][1], qf[0][ks][mt][2], qf[0][ks][mt][3],
                                    bf[nt][0], bf[nt][1]);
                        else
                            MMA_F16(c2[mt][nt][0], c2[mt][nt][1], c2[mt][nt][2], c2[mt][nt][3],
                                    qf[1][ks][mt][0], qf[1][ks][mt][1], qf[1][ks][mt][2], qf[1][ks][mt][3],
                                    bf[nt][0], bf[nt][1]);
                    }
            }
        }

        // packed exp2 -> P A-fragments (single 16-key step) + fp32 row sums
        uint32_t pa1[2][4], pa2[2][4];
        #pragma unroll
        for (int mt = 0; mt < 2; mt++) {
            pa1[mt][0] = ex2h2(c1[mt][0][0], c1[mt][0][1]);
            pa1[mt][1] = ex2h2(c1[mt][0][2], c1[mt][0][3]);
            pa1[mt][2] = ex2h2(c1[mt][1][0], c1[mt][1][1]);
            pa1[mt][3] = ex2h2(c1[mt][1][2], c1[mt][1][3]);
            pa2[mt][0] = ex2h2(c2[mt][0][0], c2[mt][0][1]);
            pa2[mt][1] = ex2h2(c2[mt][0][2], c2[mt][0][3]);
            pa2[mt][2] = ex2h2(c2[mt][1][0], c2[mt][1][1]);
            pa2[mt][3] = ex2h2(c2[mt][1][2], c2[mt][1][3]);
            float2 f;
            f = __half22float2(__hadd2(u2h(pa1[mt][0]), u2h(pa1[mt][2])));
            sp1[mt][0] += f.x + f.y;
            f = __half22float2(__hadd2(u2h(pa1[mt][1]), u2h(pa1[mt][3])));
            sp1[mt][1] += f.x + f.y;
            f = __half22float2(__hadd2(u2h(pa2[mt][0]), u2h(pa2[mt][2])));
            sp2[mt][0] += f.x + f.y;
            f = __half22float2(__hadd2(u2h(pa2[mt][1]), u2h(pa2[mt][3])));
            sp2[mt][1] += f.x + f.y;
        }

        // PV: contract warp's 16 keys over full d=64
        {
            uint32_t bf[8][2];
            #pragma unroll
            for (int np = 0; np < 4; np++) {
                uint32_t addr = vb + (uint32_t)((key0 + br + bk) * AH + np * 16 + vd) * 2;
                LDSM_X4T(bf[np*2][0], bf[np*2][1], bf[np*2+1][0], bf[np*2+1][1], addr);
            }
            #pragma unroll
            for (int mt = 0; mt < 2; mt++)
                #pragma unroll
                for (int nt = 0; nt < 8; nt++) {
                    MMA_F16(o1[mt][nt][0], o1[mt][nt][1], o1[mt][nt][2], o1[mt][nt][3],
                            pa1[mt][0], pa1[mt][1], pa1[mt][2], pa1[mt][3],
                            bf[nt][0], bf[nt][1]);
                    MMA_F16(o2[mt][nt][0], o2[mt][nt][1], o2[mt][nt][2], o2[mt][nt][3],
                            pa2[mt][0], pa2[mt][1], pa2[mt][2], pa2[mt][3],
                            bf[nt][0], bf[nt][1]);
                }
        }
    }

    // row sums: quad butterfly + atomic (all 4 key groups contribute)
    #pragma unroll
    for (int mt = 0; mt < 2; mt++)
        #pragma unroll
        for (int hf = 0; hf < 2; hf++) {
            float v1 = sp1[mt][hf], v2 = sp2[mt][hf];
            v1 += __shfl_xor_sync(0xffffffffu, v1, 1);
            v1 += __shfl_xor_sync(0xffffffffu, v1, 2);
            v2 += __shfl_xor_sync(0xffffffffu, v2, 1);
            v2 += __shfl_xor_sync(0xffffffffu, v2, 2);
            if ((lane & 3) == 0) {
                int row = wm + mt * 16 + hf * 8 + qrow;
                atomicAdd(&ssum1[row], v1);
                atomicAdd(&ssum2[row], v2);
            }
        }
    __syncthreads();

    // per-warp combined partial: v = o1/sum1 - lam*o2/sum2
    float lamv = g_lam[0];
    #pragma unroll
    for (int mt = 0; mt < 2; mt++)
        #pragma unroll
        for (int hf = 0; hf < 2; hf++) {
            int row = wm + mt * 16 + hf * 8 + qrow;
            float inv1 = 1.0f / ssum1[row];
            float inv2 = lamv / ssum2[row];
            #pragma unroll
            for (int nt = 0; nt < 8; nt++) {
                o1[mt][nt][hf*2+0] = o1[mt][nt][hf*2+0] * inv1 - o2[mt][nt][hf*2+0] * inv2;
                o1[mt][nt][hf*2+1] = o1[mt][nt][hf*2+1] * inv1 - o2[mt][nt][hf*2+1] * inv2;
            }
        }

    // cross key-group reduction: KG 1..3 store to regions, KG 0 combines
    if (wgn >= 1) {
        float* reg = obuf + (wgn - 1) * 64 * 64;
        #pragma unroll
        for (int mt = 0; mt < 2; mt++)
            #pragma unroll
            for (int hf = 0; hf < 2; hf++) {
                int row = wm + mt * 16 + hf * 8 + qrow;
                #pragma unroll
                for (int nt = 0; nt < 8; nt++) {
                    float2 p; p.x = o1[mt][nt][hf*2+0]; p.y = o1[mt][nt][hf*2+1];
                    *(float2*)&reg[row * 64 + nt * 8 + qcol] = p;
                }
            }
    }
    __syncthreads();
    if (wgn == 0) {
        #pragma unroll
        for (int mt = 0; mt < 2; mt++)
            #pragma unroll
            for (int hf = 0; hf < 2; hf++) {
                int row = wm + mt * 16 + hf * 8 + qrow;
                float sq = 0.f;
                #pragma unroll
                for (int nt = 0; nt < 8; nt++) {
                    int off = row * 64 + nt * 8 + qcol;
                    float2 p0 = *(const float2*)&obuf[off];
                    float2 p1 = *(const float2*)&obuf[64 * 64 + off];
                    float2 p2 = *(const float2*)&obuf[2 * 64 * 64 + off];
                    float v0 = o1[mt][nt][hf*2+0] + p0.x + p1.x + p2.x;
                    float v1 = o1[mt][nt][hf*2+1] + p0.y + p1.y + p2.y;
                    o1[mt][nt][hf*2+0] = v0;
                    o1[mt][nt][hf*2+1] = v1;
                    sq += v0 * v0 + v1 * v1;
                }
                sq += __shfl_xor_sync(0xffffffffu, sq, 1);
                sq += __shfl_xor_sync(0xffffffffu, sq, 2);
                float sc = rsqrtf(sq * (1.0f / 64.0f) + EPSF) * (1.0f - LAMBDA_INIT);
                #pragma unroll
                for (int nt = 0; nt < 8; nt++) {
                    int col = nt * 8 + qcol;
                    float vx = o1[mt][nt][hf*2+0] * sc * subw[col];
                    float vy = o1[mt][nt][hf*2+1] * sc * subw[col + 1];
                    *(__half2*)(O + base + (size_t)(n0 + row) * DD + h * 64 + col) =
                        __floats2half2_rn(vx, vy);
                }
            }
    }
}

// ---------------- host ------------------------------------------------------
template <typename T>
static T* symaddr(const void* sym) {
    void* p = nullptr;
    cudaGetSymbolAddress(&p, sym);
    return (T*)p;
}

extern "C" void kernel_launch(void* const* d_in, const int* in_sizes, int n_in,
                              void* d_out, int out_size) {
    const float* x      = (const float*)d_in[0];
    const float* Wq     = (const float*)d_in[1];
    const float* Wk     = (const float*)d_in[2];
    const float* Wv     = (const float*)d_in[3];
    const float* Wo     = (const float*)d_in[4];
    const float* lq1    = (const float*)d_in[5];
    const float* lk1    = (const float*)d_in[6];
    const float* lq2    = (const float*)d_in[7];
    const float* lk2    = (const float*)d_in[8];
    const float* subw   = (const float*)d_in[9];
    const float* n1_w   = (const float*)d_in[10];
    const float* n1_b   = (const float*)d_in[11];
    const float* n2_w   = (const float*)d_in[12];
    const float* n2_b   = (const float*)d_in[13];
    const float* mln1_w = (const float*)d_in[14];
    const float* mln1_b = (const float*)d_in[15];
    const float* mW1    = (const float*)d_in[16];
    const float* mb1    = (const float*)d_in[17];
    const float* mln2_w = (const float*)d_in[18];
    const float* mln2_b = (const float*)d_in[19];
    const float* mW2    = (const float*)d_in[20];
    const float* mb2    = (const float*)d_in[21];
    float* out = (float*)d_out;

    __half* p_xnh = symaddr<__half>(g_xnh);
    __half* p_aoh = symaddr<__half>(g_aoh);
    __half* p_zh  = symaddr<__half>(g_zh);
    __half* p_z1h = symaddr<__half>(g_z1h);
    __half* p_z2h = symaddr<__half>(g_z2h);
    __half* p_Woh = symaddr<__half>(g_Woh);
    __half* p_W1h = symaddr<__half>(g_W1h);
    __half* p_W2h = symaddr<__half>(g_W2h);
    float*  p_a   = symaddr<float>(g_a);
    float*  p_h   = symaddr<float>(g_h);

    cudaFuncSetAttribute(gemm_h, cudaFuncAttributeMaxDynamicSharedMemorySize, GEMM_SMEM);
    cudaFuncSetAttribute(qkv_h,  cudaFuncAttributeMaxDynamicSharedMemorySize, GEMM_SMEM);
    cudaFuncSetAttribute(attn_h, cudaFuncAttributeMaxDynamicSharedMemorySize, ATTN_SMEM);

    cvt_weights<<<(DFF * DD + 255) / 256, 256>>>(Wq, Wk, Wv, Wo, mW1, mW2,
                                                 lq1, lk1, lq2, lk2);

    ln_kernel<<<ROWS, 256>>>(x, n1_w, n1_b, nullptr, p_xnh, DD, 1);

    dim3 gQKV(12, ROWS / 128);
    qkv_h<<<gQKV, 256, GEMM_SMEM>>>(p_xnh);

    dim3 gA(NN / 64, HEADS, BB);           // 16 x 8 x 8 = 1024
    attn_h<<<gA, 256, ATTN_SMEM>>>(subw, p_aoh);

    dim3 gP(DD / 128, ROWS / 128);
    gemm_h<<<gP, 256, GEMM_SMEM>>>(p_aoh, p_Woh, nullptr, nullptr, p_a, DD, DD, 0);

    ln_fuse2<<<ROWS, 256>>>(p_a, x, n2_w, n2_b, mln1_w, mln1_b, p_h, p_zh);

    dim3 gM1(DFF / 128, ROWS / 128);
    gemm_h<<<gM1, 256, GEMM_SMEM>>>(p_zh, p_W1h, mb1, nullptr, p_z1h, DFF, DD, 5);

    ln_kernel<<<ROWS, 256>>>(p_z1h, mln2_w, mln2_b, nullptr, p_z2h, DFF, 3);

    gemm_h<<<gP, 256, GEMM_SMEM>>>(p_z2h, p_W2h, mb2, p_h, out, DD, DFF, 3);
}

// round 16
// speedup vs baseline: 1.0408x; 1.0408x over previous
#include <cuda_runtime.h>
#include <cuda_fp16.h>
#include <math.h>
#include <stdint.h>

static const int BB   = 8;
static const int NN   = 1024;
static const int DD   = 512;
static const int HEADS= 8;
static const int DFF  = 2048;
static const int ROWS = BB * NN;        // 8192
#define EPSF 1e-5f
#define LAMBDA_INIT 0.2f

// ---------------- scratch ---------------------------------------------------
__device__ float  g_lam[1];
__device__ __half g_xnh[ROWS * DD];
__device__ __half g_qh [ROWS * DD];
__device__ __half g_kh [ROWS * DD];
__device__ __half g_vh [ROWS * DD];
__device__ __half g_aoh[ROWS * DD];
__device__ float  g_a  [ROWS * DD];
__device__ float  g_h  [ROWS * DD];
__device__ __half g_zh [ROWS * DD];
__device__ __half g_z1h[ROWS * DFF];
__device__ __half g_z2h[ROWS * DFF];
__device__ __half g_Wqh[DD * DD];
__device__ __half g_Wkh[DD * DD];
__device__ __half g_Wvh[DD * DD];
__device__ __half g_Woh[DD * DD];
__device__ __half g_W1h[DFF * DD];
__device__ __half g_W2h[DD * DFF];

// ---------------- helpers ----------------------------------------------------
__device__ __forceinline__ uint32_t smem_u32(const void* p) {
    uint32_t a;
    asm("{ .reg .u64 t; cvta.to.shared.u64 t, %1; cvt.u32.u64 %0, t; }" : "=r"(a) : "l"(p));
    return a;
}
__device__ __forceinline__ __half2 u2h(uint32_t u) { return *(__half2*)&u; }
__device__ __forceinline__ uint32_t ex2h2(float a, float b) {
    __half2 t = __floats2half2_rn(a, b);
    uint32_t u = *(uint32_t*)&t, r;
    asm("ex2.approx.f16x2 %0, %1;" : "=r"(r) : "r"(u));
    return r;
}
#define CPA16(dst, src) asm volatile("cp.async.cg.shared.global [%0], [%1], 16;" :: "r"(dst), "l"(src) : "memory")
#define CP_COMMIT()     asm volatile("cp.async.commit_group;" ::: "memory")
#define CP_WAIT1()      asm volatile("cp.async.wait_group 1;" ::: "memory")
#define LDSM_X4(r0,r1,r2,r3,addr) \
    asm volatile("ldmatrix.sync.aligned.m8n8.x4.shared.b16 {%0,%1,%2,%3}, [%4];" \
                 : "=r"(r0),"=r"(r1),"=r"(r2),"=r"(r3) : "r"(addr))
#define LDSM_X4T(r0,r1,r2,r3,addr) \
    asm volatile("ldmatrix.sync.aligned.m8n8.x4.trans.shared.b16 {%0,%1,%2,%3}, [%4];" \
                 : "=r"(r0),"=r"(r1),"=r"(r2),"=r"(r3) : "r"(addr))
#define MMA_F16(c0,c1,c2,c3,a0,a1,a2,a3,b0,b1) \
    asm volatile("mma.sync.aligned.m16n8k16.row.col.f32.f16.f16.f32 " \
                 "{%0,%1,%2,%3}, {%4,%5,%6,%7}, {%8,%9}, {%0,%1,%2,%3};" \
                 : "+f"(c0),"+f"(c1),"+f"(c2),"+f"(c3) \
                 : "r"(a0),"r"(a1),"r"(a2),"r"(a3),"r"(b0),"r"(b1))

// ---------------- weights fp32 -> fp16 (+ lambda in block 0) -----------------
__global__ void cvt_weights(const float* __restrict__ Wq, const float* __restrict__ Wk,
                            const float* __restrict__ Wv, const float* __restrict__ Wo,
                            const float* __restrict__ W1, const float* __restrict__ W2,
                            const float* __restrict__ lq1, const float* __restrict__ lk1,
                            const float* __restrict__ lq2, const float* __restrict__ lk2) {
    if (blockIdx.x == 0 && threadIdx.x < 32) {
        int t = threadIdx.x;
        float a = lq1[t] * lk1[t];
        float b = lq2[t] * lk2[t];
        #pragma unroll
        for (int o = 16; o; o >>= 1) {
            a += __shfl_xor_sync(0xffffffffu, a, o);
            b += __shfl_xor_sync(0xffffffffu, b, o);
        }
        if (t == 0) g_lam[0] = expf(a) - expf(b) + LAMBDA_INIT;
    }
    int i = blockIdx.x * 256 + threadIdx.x;
    if (i < DD * DD) {
        g_Wqh[i] = __float2half_rn(Wq[i]);
        g_Wkh[i] = __float2half_rn(Wk[i]);
        g_Wvh[i] = __float2half_rn(Wv[i]);
        g_Woh[i] = __float2half_rn(Wo[i]);
    }
    if (i < DFF * DD) {
        g_W1h[i] = __float2half_rn(W1[i]);
        g_W2h[i] = __float2half_rn(W2[i]);
    }
}

// ---------------- LayerNorm; flags: bit0 = half out, bit1 = half in ---------
__global__ void ln_kernel(const void* __restrict__ Xv, const float* __restrict__ w,
                          const float* __restrict__ bvec, const float* __restrict__ res,
                          void* __restrict__ Y, int dim, int flags) {
    int row = blockIdx.x;
    int t   = threadIdx.x;
    int cnt = dim >> 8;
    float xi[8];
    float s = 0.f;
    if (flags & 2) {
        const __half* xr = (const __half*)Xv + (size_t)row * dim;
        for (int i = 0; i < cnt; i++) { xi[i] = __half2float(xr[t + 256 * i]); s += xi[i]; }
    } else {
        const float* xr = (const float*)Xv + (size_t)row * dim;
        for (int i = 0; i < cnt; i++) { xi[i] = xr[t + 256 * i]; s += xi[i]; }
    }

    __shared__ float red[8];
    #pragma unroll
    for (int o = 16; o; o >>= 1) s += __shfl_xor_sync(0xffffffffu, s, o);
    if ((t & 31) == 0) red[t >> 5] = s;
    __syncthreads();
    float tot = 0.f;
    #pragma unroll
    for (int i = 0; i < 8; i++) tot += red[i];
    float mu = tot / (float)dim;

    float v = 0.f;
    for (int i = 0; i < cnt; i++) { float d = xi[i] - mu; v += d * d; }
    __syncthreads();
    #pragma unroll
    for (int o = 16; o; o >>= 1) v += __shfl_xor_sync(0xffffffffu, v, o);
    if ((t & 31) == 0) red[t >> 5] = v;
    __syncthreads();
    float vt = 0.f;
    #pragma unroll
    for (int i = 0; i < 8; i++) vt += red[i];
    float rstd = rsqrtf(vt / (float)dim + EPSF);

    const float* rr = res ? res + (size_t)row * dim : nullptr;
    for (int i = 0; i < cnt; i++) {
        int c = t + 256 * i;
        float y = (xi[i] - mu) * rstd * w[c] + bvec[c];
        if (rr) y += rr[c];
        if (flags & 1) ((__half*)Y)[(size_t)row * dim + c] = __float2half_rn(y);
        else           ((float*)Y)[(size_t)row * dim + c] = y;
    }
}

// ---------------- fused: h = LN(a)+x (fp32), zh = LN(h) (fp16) --------------
__global__ void ln_fuse2(const float* __restrict__ A, const float* __restrict__ x,
                         const float* __restrict__ n2w, const float* __restrict__ n2b,
                         const float* __restrict__ m1w, const float* __restrict__ m1b,
                         float* __restrict__ H, __half* __restrict__ Z) {
    int row = blockIdx.x;
    int t   = threadIdx.x;
    const float* ar = A + (size_t)row * DD;
    float a0 = ar[t], a1 = ar[t + 256];

    __shared__ float red[8];
    float s = a0 + a1;
    #pragma unroll
    for (int o = 16; o; o >>= 1) s += __shfl_xor_sync(0xffffffffu, s, o);
    if ((t & 31) == 0) red[t >> 5] = s;
    __syncthreads();
    float tot = 0.f;
    #pragma unroll
    for (int i = 0; i < 8; i++) tot += red[i];
    float mu = tot * (1.0f / DD);
    float d0 = a0 - mu, d1 = a1 - mu;
    float v = d0 * d0 + d1 * d1;
    __syncthreads();
    #pragma unroll
    for (int o = 16; o; o >>= 1) v += __shfl_xor_sync(0xffffffffu, v, o);
    if ((t & 31) == 0) red[t >> 5] = v;
    __syncthreads();
    float vt = 0.f;
    #pragma unroll
    for (int i = 0; i < 8; i++) vt += red[i];
    float rstd = rsqrtf(vt * (1.0f / DD) + EPSF);

    int c0 = t, c1 = t + 256;
    float h0 = d0 * rstd * n2w[c0] + n2b[c0] + x[(size_t)row * DD + c0];
    float h1 = d1 * rstd * n2w[c1] + n2b[c1] + x[(size_t)row * DD + c1];
    H[(size_t)row * DD + c0] = h0;
    H[(size_t)row * DD + c1] = h1;

    float s2 = h0 + h1;
    __syncthreads();
    #pragma unroll
    for (int o = 16; o; o >>= 1) s2 += __shfl_xor_sync(0xffffffffu, s2, o);
    if ((t & 31) == 0) red[t >> 5] = s2;
    __syncthreads();
    float tot2 = 0.f;
    #pragma unroll
    for (int i = 0; i < 8; i++) tot2 += red[i];
    float mu2 = tot2 * (1.0f / DD);
    float e0 = h0 - mu2, e1 = h1 - mu2;
    float v2 = e0 * e0 + e1 * e1;
    __syncthreads();
    #pragma unroll
    for (int o = 16; o; o >>= 1) v2 += __shfl_xor_sync(0xffffffffu, v2, o);
    if ((t & 31) == 0) red[t >> 5] = v2;
    __syncthreads();
    float vt2 = 0.f;
    #pragma unroll
    for (int i = 0; i < 8; i++) vt2 += red[i];
    float rstd2 = rsqrtf(vt2 * (1.0f / DD) + EPSF);

    Z[(size_t)row * DD + c0] = __float2half_rn(e0 * rstd2 * m1w[c0] + m1b[c0]);
    Z[(size_t)row * DD + c1] = __float2half_rn(e1 * rstd2 * m1w[c1] + m1b[c1]);
}

// ---------------- fp16 GEMM (128x128, 3-stage, 2 CTA/SM, paired-B x4) --------
// epi: 0 f32, 2 gelu+bias f32, 3 bias+res f32, 4 half*oscale, 5 gelu+bias half
#define HST 72
#define STG_H (128 * HST)
#define GEMM_SMEM (3 * 2 * STG_H * 2)

__device__ __forceinline__ void gemm_h_issue(
        const __half* A, const __half* W, int K, int bm, int bn,
        uint32_t sb, int t, int ch, int s) {
    const __half* Ap = A + (size_t)bm * K + ch * 64;
    const __half* Wp = W + (size_t)bn * K + ch * 64;
    uint32_t ab = sb + (uint32_t)((s * 2 + 0) * STG_H) * 2;
    uint32_t wb = sb + (uint32_t)((s * 2 + 1) * STG_H) * 2;
    #pragma unroll
    for (int i = 0; i < 4; i++) {
        int f = i * 256 + t;
        int row = f >> 3, c = f & 7;
        CPA16(ab + (uint32_t)(row * HST + c * 8) * 2, Ap + (size_t)row * K + c * 8);
        CPA16(wb + (uint32_t)(row * HST + c * 8) * 2, Wp + (size_t)row * K + c * 8);
    }
}

__device__ __forceinline__ void gemm_h_core(
        const __half* __restrict__ A, const __half* __restrict__ W,
        const float* __restrict__ bias, const float* __restrict__ res,
        void* __restrict__ Cout, int Nn, int K, int epi, float oscale,
        int bm, int bn, uint32_t sb, int t) {
    int lane = t & 31, wid = t >> 5;
    int warp_m = (wid & 1) * 64;
    int warp_n = (wid >> 1) * 32;
    int ar = lane & 15;
    int ak = (lane >> 4) * 8;
    int brr = (lane & 7) + ((lane >> 4) << 3);
    int bkk = ((lane >> 3) & 1) * 8;

    float c[16][4];
    #pragma unroll
    for (int i = 0; i < 16; i++)
        #pragma unroll
        for (int j = 0; j < 4; j++) c[i][j] = 0.f;

    const int nc = K >> 6;
    gemm_h_issue(A, W, K, bm, bn, sb, t, 0, 0); CP_COMMIT();
    gemm_h_issue(A, W, K, bm, bn, sb, t, 1, 1); CP_COMMIT();

    for (int ch = 0; ch < nc; ch++) {
        CP_WAIT1();
        __syncthreads();
        if (ch + 2 < nc) gemm_h_issue(A, W, K, bm, bn, sb, t, ch + 2, (ch + 2) % 3);
        CP_COMMIT();

        int s = ch % 3;
        uint32_t ab = sb + (uint32_t)((s * 2 + 0) * STG_H) * 2;
        uint32_t wb = sb + (uint32_t)((s * 2 + 1) * STG_H) * 2;
        #pragma unroll
        for (int ks = 0; ks < 4; ks++) {
            int k0 = ks * 16;
            uint32_t af[4][4];
            #pragma unroll
            for (int mt = 0; mt < 4; mt++) {
                uint32_t addr = ab + (uint32_t)((warp_m + mt * 16 + ar) * HST + k0 + ak) * 2;
                LDSM_X4(af[mt][0], af[mt][1], af[mt][2], af[mt][3], addr);
            }
            uint32_t bf[4][2];
            #pragma unroll
            for (int np = 0; np < 2; np++) {
                uint32_t addr = wb + (uint32_t)((warp_n + np * 16 + brr) * HST + k0 + bkk) * 2;
                LDSM_X4(bf[np*2][0], bf[np*2][1], bf[np*2+1][0], bf[np*2+1][1], addr);
            }
            #pragma unroll
            for (int mt = 0; mt < 4; mt++)
                #pragma unroll
                for (int nt = 0; nt < 4; nt++)
                    MMA_F16(c[mt*4+nt][0], c[mt*4+nt][1], c[mt*4+nt][2], c[mt*4+nt][3],
                            af[mt][0], af[mt][1], af[mt][2], af[mt][3],
                            bf[nt][0], bf[nt][1]);
        }
    }

    int qrow = lane >> 2;
    int qcol = (lane & 3) * 2;
    #pragma unroll
    for (int mt = 0; mt < 4; mt++) {
        #pragma unroll
        for (int nt = 0; nt < 4; nt++) {
            int idx = mt * 4 + nt;
            int col = bn + warp_n + nt * 8 + qcol;
            #pragma unroll
            for (int hf = 0; hf < 2; hf++) {
                int row = bm + warp_m + mt * 16 + qrow + hf * 8;
                float v0 = c[idx][hf * 2 + 0];
                float v1 = c[idx][hf * 2 + 1];
                if (epi == 2 || epi == 3 || epi == 5) { v0 += bias[col]; v1 += bias[col + 1]; }
                if (epi == 2 || epi == 5) {
                    v0 = 0.5f * v0 * (1.0f + erff(v0 * 0.70710678118654752f));
                    v1 = 0.5f * v1 * (1.0f + erff(v1 * 0.70710678118654752f));
                }
                if (epi == 3) {
                    const float* rp = res + (size_t)row * Nn + col;
                    v0 += rp[0]; v1 += rp[1];
                }
                if (epi == 4 || epi == 5) {
                    *(__half2*)((__half*)Cout + (size_t)row * Nn + col) =
                        __floats2half2_rn(v0 * oscale, v1 * oscale);
                } else {
                    float2 o; o.x = v0; o.y = v1;
                    *(float2*)((float*)Cout + (size_t)row * Nn + col) = o;
                }
            }
        }
    }
}

__global__ __launch_bounds__(256, 2) void gemm_h(
        const __half* __restrict__ A, const __half* __restrict__ W,
        const float* __restrict__ bias, const float* __restrict__ res,
        void* __restrict__ Cout, int Nn, int K, int epi) {
    extern __shared__ __half smh[];
    gemm_h_core(A, W, bias, res, Cout, Nn, K, epi, 1.0f,
                blockIdx.y * 128, blockIdx.x * 128, smem_u32(smh), threadIdx.x);
}

__global__ __launch_bounds__(256, 2) void qkv_h(const __half* __restrict__ A) {
    extern __shared__ __half smh[];
    int sel = blockIdx.x >> 2;
    const __half* W = (sel == 0) ? g_Wqh : (sel == 1) ? g_Wkh : g_Wvh;
    __half* C       = (sel == 0) ? g_qh  : (sel == 1) ? g_kh  : g_vh;
    float sc = (sel == 0) ? (0.17677669529663687f * 1.4426950408889634f) : 1.0f;
    gemm_h_core(A, W, nullptr, nullptr, C, DD, DD, 4, sc,
                blockIdx.y * 128, (blockIdx.x & 3) * 128, smem_u32(smh), threadIdx.x);
}

// ---------------- fp16 differential attention, P-in-regs + hoisted Q --------
// grid (N/128, HEADS, B) = 512, 256 threads (8 warps: 4M x 2 key-groups).
#define AH 72
#define Q_OFF  0
#define K_OFF  (128 * AH)
#define V_OFF  (K_OFF + 3 * 64 * AH)
#define ATT_H  (V_OFF + 3 * 64 * AH)
#define OBUF_B (ATT_H * 2)
#define SSUM_B (OBUF_B + 128 * 64 * 4)
#define ATTN_SMEM (SSUM_B + 2 * 128 * 4)

__device__ __forceinline__ void attn_issue_kv(const __half* Kg, const __half* Vg,
                                              uint32_t sb, int t, int kt) {
    int m0 = kt * 64;
    int bufo = (kt % 3) * 64 * AH;
    #pragma unroll
    for (int i = 0; i < 2; i++) {
        int f = i * 256 + t;
        int row = f >> 3, c = f & 7;
        CPA16(sb + (uint32_t)(K_OFF + bufo + row * AH + c * 8) * 2, Kg + (size_t)(m0 + row) * DD + c * 8);
        CPA16(sb + (uint32_t)(V_OFF + bufo + row * AH + c * 8) * 2, Vg + (size_t)(m0 + row) * DD + c * 8);
    }
}

__global__ __launch_bounds__(256, 1) void attn_h(const float* __restrict__ subw,
                                                 __half* __restrict__ O) {
    extern __shared__ __half smh[];
    uint32_t sb = smem_u32(smh);
    float* obuf  = (float*)((char*)smh + OBUF_B);
    float* ssum1 = (float*)((char*)smh + SSUM_B);
    float* ssum2 = ssum1 + 128;

    int n0 = blockIdx.x * 128;
    int h  = blockIdx.y;
    int b  = blockIdx.z;
    int t  = threadIdx.x;
    int lane = t & 31, wid = t >> 5;
    size_t base = (size_t)b * NN * DD;
    const __half* Qg = g_qh + base + h * 64;
    const __half* Kg = g_kh + base + h * 64;
    const __half* Vg = g_vh + base + h * 64;

    int wm  = (wid & 3) * 32;
    int wgn = (wid >> 2);
    int ar = lane & 15;
    int ak = (lane >> 4) * 8;
    int br = lane & 7;
    int bk = ((lane >> 3) & 1) * 8;
    int brr = (lane & 7) + ((lane >> 4) << 3);
    int bkk = ((lane >> 3) & 1) * 8;
    int vd  = (lane >> 4) << 3;
    int qrow = lane >> 2;
    int qcol = (lane & 3) * 2;

    #pragma unroll
    for (int i = 0; i < 4; i++) {
        int f = i * 256 + t;
        int q = f >> 3, c = f & 7;
        CPA16(sb + (uint32_t)(Q_OFF + q * AH + c * 8) * 2, Qg + (size_t)(n0 + q) * DD + c * 8);
    }
    attn_issue_kv(Kg, Vg, sb, t, 0);
    CP_COMMIT();
    attn_issue_kv(Kg, Vg, sb, t, 1);
    CP_COMMIT();

    if (t < 128) { ssum1[t] = 0.f; ssum2[t] = 0.f; }

    float o1[2][8][4], o2[2][8][4];
    #pragma unroll
    for (int mt = 0; mt < 2; mt++)
        #pragma unroll
        for (int nt = 0; nt < 8; nt++)
            #pragma unroll
            for (int i = 0; i < 4; i++) { o1[mt][nt][i] = 0.f; o2[mt][nt][i] = 0.f; }
    float sp1[2][2] = {{0.f,0.f},{0.f,0.f}};
    float sp2[2][2] = {{0.f,0.f},{0.f,0.f}};

    uint32_t qb = sb + (uint32_t)Q_OFF * 2;
    uint32_t qf[2][2][2][4];   // [sub][ks][mt][frag] — loaded once

    for (int kt = 0; kt < 16; kt++) {
        CP_WAIT1();
        __syncthreads();
        if (kt + 2 < 16) attn_issue_kv(Kg, Vg, sb, t, kt + 2);
        CP_COMMIT();
        if (kt == 0) {
            #pragma unroll
            for (int sub = 0; sub < 2; sub++)
                #pragma unroll
                for (int ks = 0; ks < 2; ks++)
                    #pragma unroll
                    for (int mt = 0; mt < 2; mt++) {
                        uint32_t addr = qb + (uint32_t)((wm + mt * 16 + ar) * AH + sub * 32 + ks * 16 + ak) * 2;
                        LDSM_X4(qf[sub][ks][mt][0], qf[sub][ks][mt][1],
                                qf[sub][ks][mt][2], qf[sub][ks][mt][3], addr);
                    }
        }

        uint32_t kb = sb + (uint32_t)(K_OFF + (kt % 3) * 64 * AH) * 2;
        uint32_t vb = sb + (uint32_t)(V_OFF + (kt % 3) * 64 * AH) * 2;

        float c1[2][4][4], c2[2][4][4];
        #pragma unroll
        for (int mt = 0; mt < 2; mt++)
            #pragma unroll
            for (int nt = 0; nt < 4; nt++)
                #pragma unroll
                for (int i = 0; i < 4; i++) { c1[mt][nt][i] = 0.f; c2[mt][nt][i] = 0.f; }

        #pragma unroll
        for (int sub = 0; sub < 2; sub++) {
            #pragma unroll
            for (int ks = 0; ks < 2; ks++) {
                int k0 = sub * 32 + ks * 16;
                uint32_t bf[4][2];
                #pragma unroll
                for (int np = 0; np < 2; np++) {
                    uint32_t addr = kb + (uint32_t)((wgn * 32 + np * 16 + brr) * AH + k0 + bkk) * 2;
                    LDSM_X4(bf[np*2][0], bf[np*2][1], bf[np*2+1][0], bf[np*2+1][1], addr);
                }
                #pragma unroll
                for (int mt = 0; mt < 2; mt++)
                    #pragma unroll
                    for (int nt = 0; nt < 4; nt++) {
                        if (sub == 0)
                            MMA_F16(c1[mt][nt][0], c1[mt][nt][1], c1[mt][nt][2], c1[mt][nt][3],
                                    qf[0][ks][mt][0], qf[0][ks][mt][1], qf[0][ks][mt][2], qf[0][ks][mt][3],
                                    bf[nt][0], bf[nt][1]);
                        else
                            MMA_F16(c2[mt][nt][0], c2[mt][nt][1], c2[mt][nt][2], c2[mt][nt][3],
                                    qf[1][ks][mt][0], qf[1][ks][mt][1], qf[1][ks][mt][2], qf[1][ks][mt][3],
                                    bf[nt][0], bf[nt][1]);
                    }
            }
        }

        // packed exp2 -> P fragments + fp32 row sums
        uint32_t pa1[2][2][4], pa2[2][2][4];
        #pragma unroll
        for (int mt = 0; mt < 2; mt++)
            #pragma unroll
            for (int j = 0; j < 2; j++) {
                pa1[mt][j][0] = ex2h2(c1[mt][2*j][0],   c1[mt][2*j][1]);
                pa1[mt][j][1] = ex2h2(c1[mt][2*j][2],   c1[mt][2*j][3]);
                pa1[mt][j][2] = ex2h2(c1[mt][2*j+1][0], c1[mt][2*j+1][1]);
                pa1[mt][j][3] = ex2h2(c1[mt][2*j+1][2], c1[mt][2*j+1][3]);
                pa2[mt][j][0] = ex2h2(c2[mt][2*j][0],   c2[mt][2*j][1]);
                pa2[mt][j][1] = ex2h2(c2[mt][2*j][2],   c2[mt][2*j][3]);
                pa2[mt][j][2] = ex2h2(c2[mt][2*j+1][0], c2[mt][2*j+1][1]);
                pa2[mt][j][3] = ex2h2(c2[mt][2*j+1][2], c2[mt][2*j+1][3]);
            }
        #pragma unroll
        for (int mt = 0; mt < 2; mt++) {
            float2 f;
            f = __half22float2(__hadd2(u2h(pa1[mt][0][0]), u2h(pa1[mt][0][2])));
            sp1[mt][0] += f.x + f.y;
            f = __half22float2(__hadd2(u2h(pa1[mt][1][0]), u2h(pa1[mt][1][2])));
            sp1[mt][0] += f.x + f.y;
            f = __half22float2(__hadd2(u2h(pa1[mt][0][1]), u2h(pa1[mt][0][3])));
            sp1[mt][1] += f.x + f.y;
            f = __half22float2(__hadd2(u2h(pa1[mt][1][1]), u2h(pa1[mt][1][3])));
            sp1[mt][1] += f.x + f.y;
            f = __half22float2(__hadd2(u2h(pa2[mt][0][0]), u2h(pa2[mt][0][2])));
            sp2[mt][0] += f.x + f.y;
            f = __half22float2(__hadd2(u2h(pa2[mt][1][0]), u2h(pa2[mt][1][2])));
            sp2[mt][0] += f.x + f.y;
            f = __half22float2(__hadd2(u2h(pa2[mt][0][1]), u2h(pa2[mt][0][3])));
            sp2[mt][1] += f.x + f.y;
            f = __half22float2(__hadd2(u2h(pa2[mt][1][1]), u2h(pa2[mt][1][3])));
            sp2[mt][1] += f.x + f.y;
        }

        // PV: paired x4 trans V loads, P from registers
        #pragma unroll
        for (int j = 0; j < 2; j++) {
            int key0 = wgn * 32 + j * 16;
            uint32_t bf[8][2];
            #pragma unroll
            for (int np = 0; np < 4; np++) {
                uint32_t addr = vb + (uint32_t)((key0 + br + bk) * AH + np * 16 + vd) * 2;
                LDSM_X4T(bf[np*2][0], bf[np*2][1], bf[np*2+1][0], bf[np*2+1][1], addr);
            }
            #pragma unroll
            for (int mt = 0; mt < 2; mt++)
                #pragma unroll
                for (int nt = 0; nt < 8; nt++) {
                    MMA_F16(o1[mt][nt][0], o1[mt][nt][1], o1[mt][nt][2], o1[mt][nt][3],
                            pa1[mt][j][0], pa1[mt][j][1], pa1[mt][j][2], pa1[mt][j][3],
                            bf[nt][0], bf[nt][1]);
                    MMA_F16(o2[mt][nt][0], o2[mt][nt][1], o2[mt][nt][2], o2[mt][nt][3],
                            pa2[mt][j][0], pa2[mt][j][1], pa2[mt][j][2], pa2[mt][j][3],
                            bf[nt][0], bf[nt][1]);
                }
        }
    }

    #pragma unroll
    for (int mt = 0; mt < 2; mt++)
        #pragma unroll
        for (int hf = 0; hf < 2; hf++) {
            float v1 = sp1[mt][hf], v2 = sp2[mt][hf];
            v1 += __shfl_xor_sync(0xffffffffu, v1, 1);
            v1 += __shfl_xor_sync(0xffffffffu, v1, 2);
            v2 += __shfl_xor_sync(0xffffffffu, v2, 1);
            v2 += __shfl_xor_sync(0xffffffffu, v2, 2);
            if ((lane & 3) == 0) {
                int row = wm + mt * 16 + hf * 8 + qrow;
                atomicAdd(&ssum1[row], v1);
                atomicAdd(&ssum2[row], v2);
            }
        }
    __syncthreads();

    float lamv = g_lam[0];
    #pragma unroll
    for (int mt = 0; mt < 2; mt++)
        #pragma unroll
        for (int hf = 0; hf < 2; hf++) {
            int row = wm + mt * 16 + hf * 8 + qrow;
            float inv1 = 1.0f / ssum1[row];
            float inv2 = lamv / ssum2[row];
            #pragma unroll
            for (int nt = 0; nt < 8; nt++) {
                o1[mt][nt][hf*2+0] = o1[mt][nt][hf*2+0] * inv1 - o2[mt][nt][hf*2+0] * inv2;
                o1[mt][nt][hf*2+1] = o1[mt][nt][hf*2+1] * inv1 - o2[mt][nt][hf*2+1] * inv2;
            }
        }

    if (wgn == 1) {
        #pragma unroll
        for (int mt = 0; mt < 2; mt++)
            #pragma unroll
            for (int hf = 0; hf < 2; hf++) {
                int row = wm + mt * 16 + hf * 8 + qrow;
                #pragma unroll
                for (int nt = 0; nt < 8; nt++) {
                    float2 p; p.x = o1[mt][nt][hf*2+0]; p.y = o1[mt][nt][hf*2+1];
                    *(float2*)&obuf[row * 64 + nt * 8 + qcol] = p;
                }
            }
    }
    __syncthreads();
    if (wgn == 0) {
        #pragma unroll
        for (int mt = 0; mt < 2; mt++)
            #pragma unroll
            for (int hf = 0; hf < 2; hf++) {
                int row = wm + mt * 16 + hf * 8 + qrow;
                float sq = 0.f;
                #pragma unroll
                for (int nt = 0; nt < 8; nt++) {
                    float2 p = *(const float2*)&obuf[row * 64 + nt * 8 + qcol];
                    float v0 = o1[mt][nt][hf*2+0] + p.x;
                    float v1 = o1[mt][nt][hf*2+1] + p.y;
                    o1[mt][nt][hf*2+0] = v0;
                    o1[mt][nt][hf*2+1] = v1;
                    sq += v0 * v0 + v1 * v1;
                }
                sq += __shfl_xor_sync(0xffffffffu, sq, 1);
                sq += __shfl_xor_sync(0xffffffffu, sq, 2);
                float sc = rsqrtf(sq * (1.0f / 64.0f) + EPSF) * (1.0f - LAMBDA_INIT);
                #pragma unroll
                for (int nt = 0; nt < 8; nt++) {
                    int col = nt * 8 + qcol;
                    float vx = o1[mt][nt][hf*2+0] * sc * subw[col];
                    float vy = o1[mt][nt][hf*2+1] * sc * subw[col + 1];
                    *(__half2*)(O + base + (size_t)(n0 + row) * DD + h * 64 + col) =
                        __floats2half2_rn(vx, vy);
                }
            }
    }
}

// ---------------- host ------------------------------------------------------
template <typename T>
static T* symaddr(const void* sym) {
    void* p = nullptr;
    cudaGetSymbolAddress(&p, sym);
    return (T*)p;
}

extern "C" void kernel_launch(void* const* d_in, const int* in_sizes, int n_in,
                              void* d_out, int out_size) {
    const float* x      = (const float*)d_in[0];
    const float* Wq     = (const float*)d_in[1];
    const float* Wk     = (const float*)d_in[2];
    const float* Wv     = (const float*)d_in[3];
    const float* Wo     = (const float*)d_in[4];
    const float* lq1    = (const float*)d_in[5];
    const float* lk1    = (const float*)d_in[6];
    const float* lq2    = (const float*)d_in[7];
    const float* lk2    = (const float*)d_in[8];
    const float* subw   = (const float*)d_in[9];
    const float* n1_w   = (const float*)d_in[10];
    const float* n1_b   = (const float*)d_in[11];
    const float* n2_w   = (const float*)d_in[12];
    const float* n2_b   = (const float*)d_in[13];
    const float* mln1_w = (const float*)d_in[14];
    const float* mln1_b = (const float*)d_in[15];
    const float* mW1    = (const float*)d_in[16];
    const float* mb1    = (const float*)d_in[17];
    const float* mln2_w = (const float*)d_in[18];
    const float* mln2_b = (const float*)d_in[19];
    const float* mW2    = (const float*)d_in[20];
    const float* mb2    = (const float*)d_in[21];
    float* out = (float*)d_out;

    __half* p_xnh = symaddr<__half>(g_xnh);
    __half* p_aoh = symaddr<__half>(g_aoh);
    __half* p_zh  = symaddr<__half>(g_zh);
    __half* p_z1h = symaddr<__half>(g_z1h);
    __half* p_z2h = symaddr<__half>(g_z2h);
    __half* p_Woh = symaddr<__half>(g_Woh);
    __half* p_W1h = symaddr<__half>(g_W1h);
    __half* p_W2h = symaddr<__half>(g_W2h);
    float*  p_a   = symaddr<float>(g_a);
    float*  p_h   = symaddr<float>(g_h);

    cudaFuncSetAttribute(gemm_h, cudaFuncAttributeMaxDynamicSharedMemorySize, GEMM_SMEM);
    cudaFuncSetAttribute(qkv_h,  cudaFuncAttributeMaxDynamicSharedMemorySize, GEMM_SMEM);
    cudaFuncSetAttribute(attn_h, cudaFuncAttributeMaxDynamicSharedMemorySize, ATTN_SMEM);

    cvt_weights<<<(DFF * DD + 255) / 256, 256>>>(Wq, Wk, Wv, Wo, mW1, mW2,
                                                 lq1, lk1, lq2, lk2);

    ln_kernel<<<ROWS, 256>>>(x, n1_w, n1_b, nullptr, p_xnh, DD, 1);

    dim3 gQKV(12, ROWS / 128);
    qkv_h<<<gQKV, 256, GEMM_SMEM>>>(p_xnh);

    dim3 gA(NN / 128, HEADS, BB);          // 8 x 8 x 8 = 512
    attn_h<<<gA, 256, ATTN_SMEM>>>(subw, p_aoh);

    dim3 gP(DD / 128, ROWS / 128);
    gemm_h<<<gP, 256, GEMM_SMEM>>>(p_aoh, p_Woh, nullptr, nullptr, p_a, DD, DD, 0);

    ln_fuse2<<<ROWS, 256>>>(p_a, x, n2_w, n2_b, mln1_w, mln1_b, p_h, p_zh);

    dim3 gM1(DFF / 128, ROWS / 128);
    gemm_h<<<gM1, 256, GEMM_SMEM>>>(p_zh, p_W1h, mb1, nullptr, p_z1h, DFF, DD, 5);

    ln_kernel<<<ROWS, 256>>>(p_z1h, mln2_w, mln2_b, nullptr, p_z2h, DFF, 3);

    gemm_h<<<gP, 256, GEMM_SMEM>>>(p_z2h, p_W2h, mb2, p_h, out, DD, DFF, 3);
}

// round 17
// speedup vs baseline: 1.0501x; 1.0090x over previous
#include <cuda_runtime.h>
#include <cuda_fp16.h>
#include <math.h>
#include <stdint.h>

static const int BB   = 8;
static const int NN   = 1024;
static const int DD   = 512;
static const int HEADS= 8;
static const int DFF  = 2048;
static const int ROWS = BB * NN;        // 8192
#define EPSF 1e-5f
#define LAMBDA_INIT 0.2f

// ---------------- scratch ---------------------------------------------------
__device__ float  g_lam[1];
__device__ __half g_xnh[ROWS * DD];
__device__ __half g_qh [ROWS * DD];
__device__ __half g_kh [ROWS * DD];
__device__ __half g_vh [ROWS * DD];
__device__ __half g_aoh[ROWS * DD];
__device__ float  g_a  [ROWS * DD];
__device__ float  g_h  [ROWS * DD];
__device__ __half g_zh [ROWS * DD];
__device__ __half g_z1h[ROWS * DFF];
__device__ __half g_z2h[ROWS * DFF];
__device__ __half g_Wqh[DD * DD];
__device__ __half g_Wkh[DD * DD];
__device__ __half g_Wvh[DD * DD];
__device__ __half g_Woh[DD * DD];
__device__ __half g_W1h[DFF * DD];
__device__ __half g_W2h[DD * DFF];

// ---------------- helpers ----------------------------------------------------
__device__ __forceinline__ uint32_t smem_u32(const void* p) {
    uint32_t a;
    asm("{ .reg .u64 t; cvta.to.shared.u64 t, %1; cvt.u32.u64 %0, t; }" : "=r"(a) : "l"(p));
    return a;
}
__device__ __forceinline__ __half2 u2h(uint32_t u) { return *(__half2*)&u; }
__device__ __forceinline__ uint32_t ex2h2(float a, float b) {
    __half2 t = __floats2half2_rn(a, b);
    uint32_t u = *(uint32_t*)&t, r;
    asm("ex2.approx.f16x2 %0, %1;" : "=r"(r) : "r"(u));
    return r;
}
#define CPA16(dst, src) asm volatile("cp.async.cg.shared.global [%0], [%1], 16;" :: "r"(dst), "l"(src) : "memory")
#define CP_COMMIT()     asm volatile("cp.async.commit_group;" ::: "memory")
#define CP_WAIT1()      asm volatile("cp.async.wait_group 1;" ::: "memory")
#define LDSM_X4(r0,r1,r2,r3,addr) \
    asm volatile("ldmatrix.sync.aligned.m8n8.x4.shared.b16 {%0,%1,%2,%3}, [%4];" \
                 : "=r"(r0),"=r"(r1),"=r"(r2),"=r"(r3) : "r"(addr))
#define LDSM_X4T(r0,r1,r2,r3,addr) \
    asm volatile("ldmatrix.sync.aligned.m8n8.x4.trans.shared.b16 {%0,%1,%2,%3}, [%4];" \
                 : "=r"(r0),"=r"(r1),"=r"(r2),"=r"(r3) : "r"(addr))
#define MMA_F16(c0,c1,c2,c3,a0,a1,a2,a3,b0,b1) \
    asm volatile("mma.sync.aligned.m16n8k16.row.col.f32.f16.f16.f32 " \
                 "{%0,%1,%2,%3}, {%4,%5,%6,%7}, {%8,%9}, {%0,%1,%2,%3};" \
                 : "+f"(c0),"+f"(c1),"+f"(c2),"+f"(c3) \
                 : "r"(a0),"r"(a1),"r"(a2),"r"(a3),"r"(b0),"r"(b1))

// ---------------- weights fp32 -> fp16 (+ lambda in block 0) -----------------
__global__ void cvt_weights(const float* __restrict__ Wq, const float* __restrict__ Wk,
                            const float* __restrict__ Wv, const float* __restrict__ Wo,
                            const float* __restrict__ W1, const float* __restrict__ W2,
                            const float* __restrict__ lq1, const float* __restrict__ lk1,
                            const float* __restrict__ lq2, const float* __restrict__ lk2) {
    if (blockIdx.x == 0 && threadIdx.x < 32) {
        int t = threadIdx.x;
        float a = lq1[t] * lk1[t];
        float b = lq2[t] * lk2[t];
        #pragma unroll
        for (int o = 16; o; o >>= 1) {
            a += __shfl_xor_sync(0xffffffffu, a, o);
            b += __shfl_xor_sync(0xffffffffu, b, o);
        }
        if (t == 0) g_lam[0] = expf(a) - expf(b) + LAMBDA_INIT;
    }
    int i = blockIdx.x * 256 + threadIdx.x;
    if (i < DD * DD) {
        g_Wqh[i] = __float2half_rn(Wq[i]);
        g_Wkh[i] = __float2half_rn(Wk[i]);
        g_Wvh[i] = __float2half_rn(Wv[i]);
        g_Woh[i] = __float2half_rn(Wo[i]);
    }
    if (i < DFF * DD) {
        g_W1h[i] = __float2half_rn(W1[i]);
        g_W2h[i] = __float2half_rn(W2[i]);
    }
}

// ---------------- LayerNorm; flags: bit0 = half out, bit1 = half in ---------
__global__ void ln_kernel(const void* __restrict__ Xv, const float* __restrict__ w,
                          const float* __restrict__ bvec, const float* __restrict__ res,
                          void* __restrict__ Y, int dim, int flags) {
    int row = blockIdx.x;
    int t   = threadIdx.x;
    int cnt = dim >> 8;
    float xi[8];
    float s = 0.f;
    if (flags & 2) {
        const __half* xr = (const __half*)Xv + (size_t)row * dim;
        for (int i = 0; i < cnt; i++) { xi[i] = __half2float(xr[t + 256 * i]); s += xi[i]; }
    } else {
        const float* xr = (const float*)Xv + (size_t)row * dim;
        for (int i = 0; i < cnt; i++) { xi[i] = xr[t + 256 * i]; s += xi[i]; }
    }

    __shared__ float red[8];
    #pragma unroll
    for (int o = 16; o; o >>= 1) s += __shfl_xor_sync(0xffffffffu, s, o);
    if ((t & 31) == 0) red[t >> 5] = s;
    __syncthreads();
    float tot = 0.f;
    #pragma unroll
    for (int i = 0; i < 8; i++) tot += red[i];
    float mu = tot / (float)dim;

    float v = 0.f;
    for (int i = 0; i < cnt; i++) { float d = xi[i] - mu; v += d * d; }
    __syncthreads();
    #pragma unroll
    for (int o = 16; o; o >>= 1) v += __shfl_xor_sync(0xffffffffu, v, o);
    if ((t & 31) == 0) red[t >> 5] = v;
    __syncthreads();
    float vt = 0.f;
    #pragma unroll
    for (int i = 0; i < 8; i++) vt += red[i];
    float rstd = rsqrtf(vt / (float)dim + EPSF);

    const float* rr = res ? res + (size_t)row * dim : nullptr;
    for (int i = 0; i < cnt; i++) {
        int c = t + 256 * i;
        float y = (xi[i] - mu) * rstd * w[c] + bvec[c];
        if (rr) y += rr[c];
        if (flags & 1) ((__half*)Y)[(size_t)row * dim + c] = __float2half_rn(y);
        else           ((float*)Y)[(size_t)row * dim + c] = y;
    }
}

// ---------------- fused: h = LN(a)+x (fp32), zh = LN(h) (fp16) --------------
__global__ void ln_fuse2(const float* __restrict__ A, const float* __restrict__ x,
                         const float* __restrict__ n2w, const float* __restrict__ n2b,
                         const float* __restrict__ m1w, const float* __restrict__ m1b,
                         float* __restrict__ H, __half* __restrict__ Z) {
    int row = blockIdx.x;
    int t   = threadIdx.x;
    const float* ar = A + (size_t)row * DD;
    float a0 = ar[t], a1 = ar[t + 256];

    __shared__ float red[8];
    float s = a0 + a1;
    #pragma unroll
    for (int o = 16; o; o >>= 1) s += __shfl_xor_sync(0xffffffffu, s, o);
    if ((t & 31) == 0) red[t >> 5] = s;
    __syncthreads();
    float tot = 0.f;
    #pragma unroll
    for (int i = 0; i < 8; i++) tot += red[i];
    float mu = tot * (1.0f / DD);
    float d0 = a0 - mu, d1 = a1 - mu;
    float v = d0 * d0 + d1 * d1;
    __syncthreads();
    #pragma unroll
    for (int o = 16; o; o >>= 1) v += __shfl_xor_sync(0xffffffffu, v, o);
    if ((t & 31) == 0) red[t >> 5] = v;
    __syncthreads();
    float vt = 0.f;
    #pragma unroll
    for (int i = 0; i < 8; i++) vt += red[i];
    float rstd = rsqrtf(vt * (1.0f / DD) + EPSF);

    int c0 = t, c1 = t + 256;
    float h0 = d0 * rstd * n2w[c0] + n2b[c0] + x[(size_t)row * DD + c0];
    float h1 = d1 * rstd * n2w[c1] + n2b[c1] + x[(size_t)row * DD + c1];
    H[(size_t)row * DD + c0] = h0;
    H[(size_t)row * DD + c1] = h1;

    float s2 = h0 + h1;
    __syncthreads();
    #pragma unroll
    for (int o = 16; o; o >>= 1) s2 += __shfl_xor_sync(0xffffffffu, s2, o);
    if ((t & 31) == 0) red[t >> 5] = s2;
    __syncthreads();
    float tot2 = 0.f;
    #pragma unroll
    for (int i = 0; i < 8; i++) tot2 += red[i];
    float mu2 = tot2 * (1.0f / DD);
    float e0 = h0 - mu2, e1 = h1 - mu2;
    float v2 = e0 * e0 + e1 * e1;
    __syncthreads();
    #pragma unroll
    for (int o = 16; o; o >>= 1) v2 += __shfl_xor_sync(0xffffffffu, v2, o);
    if ((t & 31) == 0) red[t >> 5] = v2;
    __syncthreads();
    float vt2 = 0.f;
    #pragma unroll
    for (int i = 0; i < 8; i++) vt2 += red[i];
    float rstd2 = rsqrtf(vt2 * (1.0f / DD) + EPSF);

    Z[(size_t)row * DD + c0] = __float2half_rn(e0 * rstd2 * m1w[c0] + m1b[c0]);
    Z[(size_t)row * DD + c1] = __float2half_rn(e1 * rstd2 * m1w[c1] + m1b[c1]);
}

// ---------------- fp16 GEMM (128x128, 3-stage, 2 CTA/SM, paired-B x4) --------
// epi: 0 f32, 2 gelu+bias f32, 3 bias+res f32, 4 half*oscale, 5 gelu+bias half
#define HST 72
#define STG_H (128 * HST)
#define GEMM_SMEM (3 * 2 * STG_H * 2)

__device__ __forceinline__ void gemm_h_issue(
        const __half* A, const __half* W, int K, int bm, int bn,
        uint32_t sb, int t, int ch, int s) {
    const __half* Ap = A + (size_t)bm * K + ch * 64;
    const __half* Wp = W + (size_t)bn * K + ch * 64;
    uint32_t ab = sb + (uint32_t)((s * 2 + 0) * STG_H) * 2;
    uint32_t wb = sb + (uint32_t)((s * 2 + 1) * STG_H) * 2;
    #pragma unroll
    for (int i = 0; i < 4; i++) {
        int f = i * 256 + t;
        int row = f >> 3, c = f & 7;
        CPA16(ab + (uint32_t)(row * HST + c * 8) * 2, Ap + (size_t)row * K + c * 8);
        CPA16(wb + (uint32_t)(row * HST + c * 8) * 2, Wp + (size_t)row * K + c * 8);
    }
}

__device__ __forceinline__ void gemm_h_core(
        const __half* __restrict__ A, const __half* __restrict__ W,
        const float* __restrict__ bias, const float* __restrict__ res,
        void* __restrict__ Cout, int Nn, int K, int epi, float oscale,
        int bm, int bn, uint32_t sb, int t) {
    int lane = t & 31, wid = t >> 5;
    int warp_m = (wid & 1) * 64;
    int warp_n = (wid >> 1) * 32;
    int ar = lane & 15;
    int ak = (lane >> 4) * 8;
    int brr = (lane & 7) + ((lane >> 4) << 3);
    int bkk = ((lane >> 3) & 1) * 8;

    float c[16][4];
    #pragma unroll
    for (int i = 0; i < 16; i++)
        #pragma unroll
        for (int j = 0; j < 4; j++) c[i][j] = 0.f;

    const int nc = K >> 6;
    gemm_h_issue(A, W, K, bm, bn, sb, t, 0, 0); CP_COMMIT();
    gemm_h_issue(A, W, K, bm, bn, sb, t, 1, 1); CP_COMMIT();

    for (int ch = 0; ch < nc; ch++) {
        CP_WAIT1();
        __syncthreads();
        if (ch + 2 < nc) gemm_h_issue(A, W, K, bm, bn, sb, t, ch + 2, (ch + 2) % 3);
        CP_COMMIT();

        int s = ch % 3;
        uint32_t ab = sb + (uint32_t)((s * 2 + 0) * STG_H) * 2;
        uint32_t wb = sb + (uint32_t)((s * 2 + 1) * STG_H) * 2;
        #pragma unroll
        for (int ks = 0; ks < 4; ks++) {
            int k0 = ks * 16;
            uint32_t af[4][4];
            #pragma unroll
            for (int mt = 0; mt < 4; mt++) {
                uint32_t addr = ab + (uint32_t)((warp_m + mt * 16 + ar) * HST + k0 + ak) * 2;
                LDSM_X4(af[mt][0], af[mt][1], af[mt][2], af[mt][3], addr);
            }
            uint32_t bf[4][2];
            #pragma unroll
            for (int np = 0; np < 2; np++) {
                uint32_t addr = wb + (uint32_t)((warp_n + np * 16 + brr) * HST + k0 + bkk) * 2;
                LDSM_X4(bf[np*2][0], bf[np*2][1], bf[np*2+1][0], bf[np*2+1][1], addr);
            }
            #pragma unroll
            for (int mt = 0; mt < 4; mt++)
                #pragma unroll
                for (int nt = 0; nt < 4; nt++)
                    MMA_F16(c[mt*4+nt][0], c[mt*4+nt][1], c[mt*4+nt][2], c[mt*4+nt][3],
                            af[mt][0], af[mt][1], af[mt][2], af[mt][3],
                            bf[nt][0], bf[nt][1]);
        }
    }

    int qrow = lane >> 2;
    int qcol = (lane & 3) * 2;
    #pragma unroll
    for (int mt = 0; mt < 4; mt++) {
        #pragma unroll
        for (int nt = 0; nt < 4; nt++) {
            int idx = mt * 4 + nt;
            int col = bn + warp_n + nt * 8 + qcol;
            #pragma unroll
            for (int hf = 0; hf < 2; hf++) {
                int row = bm + warp_m + mt * 16 + qrow + hf * 8;
                float v0 = c[idx][hf * 2 + 0];
                float v1 = c[idx][hf * 2 + 1];
                if (epi == 2 || epi == 3 || epi == 5) { v0 += bias[col]; v1 += bias[col + 1]; }
                if (epi == 2 || epi == 5) {
                    v0 = 0.5f * v0 * (1.0f + erff(v0 * 0.70710678118654752f));
                    v1 = 0.5f * v1 * (1.0f + erff(v1 * 0.70710678118654752f));
                }
                if (epi == 3) {
                    const float* rp = res + (size_t)row * Nn + col;
                    v0 += rp[0]; v1 += rp[1];
                }
                if (epi == 4 || epi == 5) {
                    *(__half2*)((__half*)Cout + (size_t)row * Nn + col) =
                        __floats2half2_rn(v0 * oscale, v1 * oscale);
                } else {
                    float2 o; o.x = v0; o.y = v1;
                    *(float2*)((float*)Cout + (size_t)row * Nn + col) = o;
                }
            }
        }
    }
}

__global__ __launch_bounds__(256, 2) void gemm_h(
        const __half* __restrict__ A, const __half* __restrict__ W,
        const float* __restrict__ bias, const float* __restrict__ res,
        void* __restrict__ Cout, int Nn, int K, int epi) {
    extern __shared__ __half smh[];
    gemm_h_core(A, W, bias, res, Cout, Nn, K, epi, 1.0f,
                blockIdx.y * 128, blockIdx.x * 128, smem_u32(smh), threadIdx.x);
}

__global__ __launch_bounds__(256, 2) void qkv_h(const __half* __restrict__ A) {
    extern __shared__ __half smh[];
    int sel = blockIdx.x >> 2;
    const __half* W = (sel == 0) ? g_Wqh : (sel == 1) ? g_Wkh : g_Wvh;
    __half* C       = (sel == 0) ? g_qh  : (sel == 1) ? g_kh  : g_vh;
    float sc = (sel == 0) ? (0.17677669529663687f * 1.4426950408889634f) : 1.0f;
    gemm_h_core(A, W, nullptr, nullptr, C, DD, DD, 4, sc,
                blockIdx.y * 128, (blockIdx.x & 3) * 128, smem_u32(smh), threadIdx.x);
}

// ---------------- fp16 differential attention (phase-interleaved) ------------
// grid (N/128, HEADS, B) = 512, 256 threads (8 warps: 4M x 2 key-groups).
#define AH 72
#define Q_OFF  0
#define K_OFF  (128 * AH)
#define V_OFF  (K_OFF + 3 * 64 * AH)
#define ATT_H  (V_OFF + 3 * 64 * AH)
#define OBUF_B (ATT_H * 2)
#define SSUM_B (OBUF_B + 128 * 64 * 4)
#define ATTN_SMEM (SSUM_B + 2 * 128 * 4)

__device__ __forceinline__ void attn_issue_kv(const __half* Kg, const __half* Vg,
                                              uint32_t sb, int t, int kt) {
    int m0 = kt * 64;
    int bufo = (kt % 3) * 64 * AH;
    #pragma unroll
    for (int i = 0; i < 2; i++) {
        int f = i * 256 + t;
        int row = f >> 3, c = f & 7;
        CPA16(sb + (uint32_t)(K_OFF + bufo + row * AH + c * 8) * 2, Kg + (size_t)(m0 + row) * DD + c * 8);
        CPA16(sb + (uint32_t)(V_OFF + bufo + row * AH + c * 8) * 2, Vg + (size_t)(m0 + row) * DD + c * 8);
    }
}

__global__ __launch_bounds__(256, 1) void attn_h(const float* __restrict__ subw,
                                                 __half* __restrict__ O) {
    extern __shared__ __half smh[];
    uint32_t sb = smem_u32(smh);
    float* obuf  = (float*)((char*)smh + OBUF_B);
    float* ssum1 = (float*)((char*)smh + SSUM_B);
    float* ssum2 = ssum1 + 128;

    int n0 = blockIdx.x * 128;
    int h  = blockIdx.y;
    int b  = blockIdx.z;
    int t  = threadIdx.x;
    int lane = t & 31, wid = t >> 5;
    size_t base = (size_t)b * NN * DD;
    const __half* Qg = g_qh + base + h * 64;
    const __half* Kg = g_kh + base + h * 64;
    const __half* Vg = g_vh + base + h * 64;

    int wm  = (wid & 3) * 32;
    int wgn = (wid >> 2);
    int ar = lane & 15;
    int ak = (lane >> 4) * 8;
    int br = lane & 7;
    int bk = ((lane >> 3) & 1) * 8;
    int brr = (lane & 7) + ((lane >> 4) << 3);
    int bkk = ((lane >> 3) & 1) * 8;
    int vd  = (lane >> 4) << 3;
    int qrow = lane >> 2;
    int qcol = (lane & 3) * 2;

    #pragma unroll
    for (int i = 0; i < 4; i++) {
        int f = i * 256 + t;
        int q = f >> 3, c = f & 7;
        CPA16(sb + (uint32_t)(Q_OFF + q * AH + c * 8) * 2, Qg + (size_t)(n0 + q) * DD + c * 8);
    }
    attn_issue_kv(Kg, Vg, sb, t, 0);
    CP_COMMIT();
    attn_issue_kv(Kg, Vg, sb, t, 1);
    CP_COMMIT();

    if (t < 128) { ssum1[t] = 0.f; ssum2[t] = 0.f; }

    float o1[2][8][4], o2[2][8][4];
    #pragma unroll
    for (int mt = 0; mt < 2; mt++)
        #pragma unroll
        for (int nt = 0; nt < 8; nt++)
            #pragma unroll
            for (int i = 0; i < 4; i++) { o1[mt][nt][i] = 0.f; o2[mt][nt][i] = 0.f; }
    float sp1[2][2] = {{0.f,0.f},{0.f,0.f}};
    float sp2[2][2] = {{0.f,0.f},{0.f,0.f}};

    uint32_t qb = sb + (uint32_t)Q_OFF * 2;
    uint32_t qf[2][2][2][4];   // [sub][ks][mt][frag] — loaded once

    for (int kt = 0; kt < 16; kt++) {
        CP_WAIT1();
        __syncthreads();
        if (kt + 2 < 16) attn_issue_kv(Kg, Vg, sb, t, kt + 2);
        CP_COMMIT();
        if (kt == 0) {
            #pragma unroll
            for (int sub = 0; sub < 2; sub++)
                #pragma unroll
                for (int ks = 0; ks < 2; ks++)
                    #pragma unroll
                    for (int mt = 0; mt < 2; mt++) {
                        uint32_t addr = qb + (uint32_t)((wm + mt * 16 + ar) * AH + sub * 32 + ks * 16 + ak) * 2;
                        LDSM_X4(qf[sub][ks][mt][0], qf[sub][ks][mt][1],
                                qf[sub][ks][mt][2], qf[sub][ks][mt][3], addr);
                    }
        }

        uint32_t kb = sb + (uint32_t)(K_OFF + (kt % 3) * 64 * AH) * 2;
        uint32_t vb = sb + (uint32_t)(V_OFF + (kt % 3) * 64 * AH) * 2;

        // ---- S phase, sub-head 1 ----
        float c1[2][4][4];
        #pragma unroll
        for (int mt = 0; mt < 2; mt++)
            #pragma unroll
            for (int nt = 0; nt < 4; nt++)
                #pragma unroll
                for (int i = 0; i < 4; i++) c1[mt][nt][i] = 0.f;
        #pragma unroll
        for (int ks = 0; ks < 2; ks++) {
            int k0 = ks * 16;
            uint32_t bf[4][2];
            #pragma unroll
            for (int np = 0; np < 2; np++) {
                uint32_t addr = kb + (uint32_t)((wgn * 32 + np * 16 + brr) * AH + k0 + bkk) * 2;
                LDSM_X4(bf[np*2][0], bf[np*2][1], bf[np*2+1][0], bf[np*2+1][1], addr);
            }
            #pragma unroll
            for (int mt = 0; mt < 2; mt++)
                #pragma unroll
                for (int nt = 0; nt < 4; nt++)
                    MMA_F16(c1[mt][nt][0], c1[mt][nt][1], c1[mt][nt][2], c1[mt][nt][3],
                            qf[0][ks][mt][0], qf[0][ks][mt][1], qf[0][ks][mt][2], qf[0][ks][mt][3],
                            bf[nt][0], bf[nt][1]);
        }

        // ---- exp2(c1) -> pa1 (MUFU overlaps following S2 MMAs) ----
        uint32_t pa1[2][2][4];
        #pragma unroll
        for (int mt = 0; mt < 2; mt++)
            #pragma unroll
            for (int j = 0; j < 2; j++) {
                pa1[mt][j][0] = ex2h2(c1[mt][2*j][0],   c1[mt][2*j][1]);
                pa1[mt][j][1] = ex2h2(c1[mt][2*j][2],   c1[mt][2*j][3]);
                pa1[mt][j][2] = ex2h2(c1[mt][2*j+1][0], c1[mt][2*j+1][1]);
                pa1[mt][j][3] = ex2h2(c1[mt][2*j+1][2], c1[mt][2*j+1][3]);
            }

        // ---- S phase, sub-head 2 (c1 regs reusable) ----
        float c2[2][4][4];
        #pragma unroll
        for (int mt = 0; mt < 2; mt++)
            #pragma unroll
            for (int nt = 0; nt < 4; nt++)
                #pragma unroll
                for (int i = 0; i < 4; i++) c2[mt][nt][i] = 0.f;
        #pragma unroll
        for (int ks = 0; ks < 2; ks++) {
            int k0 = 32 + ks * 16;
            uint32_t bf[4][2];
            #pragma unroll
            for (int np = 0; np < 2; np++) {
                uint32_t addr = kb + (uint32_t)((wgn * 32 + np * 16 + brr) * AH + k0 + bkk) * 2;
                LDSM_X4(bf[np*2][0], bf[np*2][1], bf[np*2+1][0], bf[np*2+1][1], addr);
            }
            #pragma unroll
            for (int mt = 0; mt < 2; mt++)
                #pragma unroll
                for (int nt = 0; nt < 4; nt++)
                    MMA_F16(c2[mt][nt][0], c2[mt][nt][1], c2[mt][nt][2], c2[mt][nt][3],
                            qf[1][ks][mt][0], qf[1][ks][mt][1], qf[1][ks][mt][2], qf[1][ks][mt][3],
                            bf[nt][0], bf[nt][1]);
        }

        // ---- sums for sub-head 1 ----
        #pragma unroll
        for (int mt = 0; mt < 2; mt++) {
            float2 f;
            f = __half22float2(__hadd2(u2h(pa1[mt][0][0]), u2h(pa1[mt][0][2])));
            sp1[mt][0] += f.x + f.y;
            f = __half22float2(__hadd2(u2h(pa1[mt][1][0]), u2h(pa1[mt][1][2])));
            sp1[mt][0] += f.x + f.y;
            f = __half22float2(__hadd2(u2h(pa1[mt][0][1]), u2h(pa1[mt][0][3])));
            sp1[mt][1] += f.x + f.y;
            f = __half22float2(__hadd2(u2h(pa1[mt][1][1]), u2h(pa1[mt][1][3])));
            sp1[mt][1] += f.x + f.y;
        }

        // ---- PV j=0 for o1 ----
        uint32_t vf[8][2];
        {
            int key0 = wgn * 32;
            #pragma unroll
            for (int np = 0; np < 4; np++) {
                uint32_t addr = vb + (uint32_t)((key0 + br + bk) * AH + np * 16 + vd) * 2;
                LDSM_X4T(vf[np*2][0], vf[np*2][1], vf[np*2+1][0], vf[np*2+1][1], addr);
            }
            #pragma unroll
            for (int mt = 0; mt < 2; mt++)
                #pragma unroll
                for (int nt = 0; nt < 8; nt++)
                    MMA_F16(o1[mt][nt][0], o1[mt][nt][1], o1[mt][nt][2], o1[mt][nt][3],
                            pa1[mt][0][0], pa1[mt][0][1], pa1[mt][0][2], pa1[mt][0][3],
                            vf[nt][0], vf[nt][1]);
        }

        // ---- exp2(c2) -> pa2 (MUFU overlaps PV MMAs) ----
        uint32_t pa2[2][2][4];
        #pragma unroll
        for (int mt = 0; mt < 2; mt++)
            #pragma unroll
            for (int j = 0; j < 2; j++) {
                pa2[mt][j][0] = ex2h2(c2[mt][2*j][0],   c2[mt][2*j][1]);
                pa2[mt][j][1] = ex2h2(c2[mt][2*j][2],   c2[mt][2*j][3]);
                pa2[mt][j][2] = ex2h2(c2[mt][2*j+1][0], c2[mt][2*j+1][1]);
                pa2[mt][j][3] = ex2h2(c2[mt][2*j+1][2], c2[mt][2*j+1][3]);
            }

        // ---- PV j=0 for o2 ----
        #pragma unroll
        for (int mt = 0; mt < 2; mt++)
            #pragma unroll
            for (int nt = 0; nt < 8; nt++)
                MMA_F16(o2[mt][nt][0], o2[mt][nt][1], o2[mt][nt][2], o2[mt][nt][3],
                        pa2[mt][0][0], pa2[mt][0][1], pa2[mt][0][2], pa2[mt][0][3],
                        vf[nt][0], vf[nt][1]);

        // ---- sums for sub-head 2 ----
        #pragma unroll
        for (int mt = 0; mt < 2; mt++) {
            float2 f;
            f = __half22float2(__hadd2(u2h(pa2[mt][0][0]), u2h(pa2[mt][0][2])));
            sp2[mt][0] += f.x + f.y;
            f = __half22float2(__hadd2(u2h(pa2[mt][1][0]), u2h(pa2[mt][1][2])));
            sp2[mt][0] += f.x + f.y;
            f = __half22float2(__hadd2(u2h(pa2[mt][0][1]), u2h(pa2[mt][0][3])));
            sp2[mt][1] += f.x + f.y;
            f = __half22float2(__hadd2(u2h(pa2[mt][1][1]), u2h(pa2[mt][1][3])));
            sp2[mt][1] += f.x + f.y;
        }

        // ---- PV j=1 for o1 and o2 ----
        {
            int key0 = wgn * 32 + 16;
            #pragma unroll
            for (int np = 0; np < 4; np++) {
                uint32_t addr = vb + (uint32_t)((key0 + br + bk) * AH + np * 16 + vd) * 2;
                LDSM_X4T(vf[np*2][0], vf[np*2][1], vf[np*2+1][0], vf[np*2+1][1], addr);
            }
            #pragma unroll
            for (int mt = 0; mt < 2; mt++)
                #pragma unroll
                for (int nt = 0; nt < 8; nt++) {
                    MMA_F16(o1[mt][nt][0], o1[mt][nt][1], o1[mt][nt][2], o1[mt][nt][3],
                            pa1[mt][1][0], pa1[mt][1][1], pa1[mt][1][2], pa1[mt][1][3],
                            vf[nt][0], vf[nt][1]);
                    MMA_F16(o2[mt][nt][0], o2[mt][nt][1], o2[mt][nt][2], o2[mt][nt][3],
                            pa2[mt][1][0], pa2[mt][1][1], pa2[mt][1][2], pa2[mt][1][3],
                            vf[nt][0], vf[nt][1]);
                }
        }
    }

    #pragma unroll
    for (int mt = 0; mt < 2; mt++)
        #pragma unroll
        for (int hf = 0; hf < 2; hf++) {
            float v1 = sp1[mt][hf], v2 = sp2[mt][hf];
            v1 += __shfl_xor_sync(0xffffffffu, v1, 1);
            v1 += __shfl_xor_sync(0xffffffffu, v1, 2);
            v2 += __shfl_xor_sync(0xffffffffu, v2, 1);
            v2 += __shfl_xor_sync(0xffffffffu, v2, 2);
            if ((lane & 3) == 0) {
                int row = wm + mt * 16 + hf * 8 + qrow;
                atomicAdd(&ssum1[row], v1);
                atomicAdd(&ssum2[row], v2);
            }
        }
    __syncthreads();

    float lamv = g_lam[0];
    #pragma unroll
    for (int mt = 0; mt < 2; mt++)
        #pragma unroll
        for (int hf = 0; hf < 2; hf++) {
            int row = wm + mt * 16 + hf * 8 + qrow;
            float inv1 = 1.0f / ssum1[row];
            float inv2 = lamv / ssum2[row];
            #pragma unroll
            for (int nt = 0; nt < 8; nt++) {
                o1[mt][nt][hf*2+0] = o1[mt][nt][hf*2+0] * inv1 - o2[mt][nt][hf*2+0] * inv2;
                o1[mt][nt][hf*2+1] = o1[mt][nt][hf*2+1] * inv1 - o2[mt][nt][hf*2+1] * inv2;
            }
        }

    if (wgn == 1) {
        #pragma unroll
        for (int mt = 0; mt < 2; mt++)
            #pragma unroll
            for (int hf = 0; hf < 2; hf++) {
                int row = wm + mt * 16 + hf * 8 + qrow;
                #pragma unroll
                for (int nt = 0; nt < 8; nt++) {
                    float2 p; p.x = o1[mt][nt][hf*2+0]; p.y = o1[mt][nt][hf*2+1];
                    *(float2*)&obuf[row * 64 + nt * 8 + qcol] = p;
                }
            }
    }
    __syncthreads();
    if (wgn == 0) {
        #pragma unroll
        for (int mt = 0; mt < 2; mt++)
            #pragma unroll
            for (int hf = 0; hf < 2; hf++) {
                int row = wm + mt * 16 + hf * 8 + qrow;
                float sq = 0.f;
                #pragma unroll
                for (int nt = 0; nt < 8; nt++) {
                    float2 p = *(const float2*)&obuf[row * 64 + nt * 8 + qcol];
                    float v0 = o1[mt][nt][hf*2+0] + p.x;
                    float v1 = o1[mt][nt][hf*2+1] + p.y;
                    o1[mt][nt][hf*2+0] = v0;
                    o1[mt][nt][hf*2+1] = v1;
                    sq += v0 * v0 + v1 * v1;
                }
                sq += __shfl_xor_sync(0xffffffffu, sq, 1);
                sq += __shfl_xor_sync(0xffffffffu, sq, 2);
                float sc = rsqrtf(sq * (1.0f / 64.0f) + EPSF) * (1.0f - LAMBDA_INIT);
                #pragma unroll
                for (int nt = 0; nt < 8; nt++) {
                    int col = nt * 8 + qcol;
                    float vx = o1[mt][nt][hf*2+0] * sc * subw[col];
                    float vy = o1[mt][nt][hf*2+1] * sc * subw[col + 1];
                    *(__half2*)(O + base + (size_t)(n0 + row) * DD + h * 64 + col) =
                        __floats2half2_rn(vx, vy);
                }
            }
    }
}

// ---------------- host ------------------------------------------------------
template <typename T>
static T* symaddr(const void* sym) {
    void* p = nullptr;
    cudaGetSymbolAddress(&p, sym);
    return (T*)p;
}

extern "C" void kernel_launch(void* const* d_in, const int* in_sizes, int n_in,
                              void* d_out, int out_size) {
    const float* x      = (const float*)d_in[0];
    const float* Wq     = (const float*)d_in[1];
    const float* Wk     = (const float*)d_in[2];
    const float* Wv     = (const float*)d_in[3];
    const float* Wo     = (const float*)d_in[4];
    const float* lq1    = (const float*)d_in[5];
    const float* lk1    = (const float*)d_in[6];
    const float* lq2    = (const float*)d_in[7];
    const float* lk2    = (const float*)d_in[8];
    const float* subw   = (const float*)d_in[9];
    const float* n1_w   = (const float*)d_in[10];
    const float* n1_b   = (const float*)d_in[11];
    const float* n2_w   = (const float*)d_in[12];
    const float* n2_b   = (const float*)d_in[13];
    const float* mln1_w = (const float*)d_in[14];
    const float* mln1_b = (const float*)d_in[15];
    const float* mW1    = (const float*)d_in[16];
    const float* mb1    = (const float*)d_in[17];
    const float* mln2_w = (const float*)d_in[18];
    const float* mln2_b = (const float*)d_in[19];
    const float* mW2    = (const float*)d_in[20];
    const float* mb2    = (const float*)d_in[21];
    float* out = (float*)d_out;

    __half* p_xnh = symaddr<__half>(g_xnh);
    __half* p_aoh = symaddr<__half>(g_aoh);
    __half* p_zh  = symaddr<__half>(g_zh);
    __half* p_z1h = symaddr<__half>(g_z1h);
    __half* p_z2h = symaddr<__half>(g_z2h);
    __half* p_Woh = symaddr<__half>(g_Woh);
    __half* p_W1h = symaddr<__half>(g_W1h);
    __half* p_W2h = symaddr<__half>(g_W2h);
    float*  p_a   = symaddr<float>(g_a);
    float*  p_h   = symaddr<float>(g_h);

    cudaFuncSetAttribute(gemm_h, cudaFuncAttributeMaxDynamicSharedMemorySize, GEMM_SMEM);
    cudaFuncSetAttribute(qkv_h,  cudaFuncAttributeMaxDynamicSharedMemorySize, GEMM_SMEM);
    cudaFuncSetAttribute(attn_h, cudaFuncAttributeMaxDynamicSharedMemorySize, ATTN_SMEM);

    cvt_weights<<<(DFF * DD + 255) / 256, 256>>>(Wq, Wk, Wv, Wo, mW1, mW2,
                                                 lq1, lk1, lq2, lk2);

    ln_kernel<<<ROWS, 256>>>(x, n1_w, n1_b, nullptr, p_xnh, DD, 1);

    dim3 gQKV(12, ROWS / 128);
    qkv_h<<<gQKV, 256, GEMM_SMEM>>>(p_xnh);

    dim3 gA(NN / 128, HEADS, BB);          // 8 x 8 x 8 = 512
    attn_h<<<gA, 256, ATTN_SMEM>>>(subw, p_aoh);

    dim3 gP(DD / 128, ROWS / 128);
    gemm_h<<<gP, 256, GEMM_SMEM>>>(p_aoh, p_Woh, nullptr, nullptr, p_a, DD, DD, 0);

    ln_fuse2<<<ROWS, 256>>>(p_a, x, n2_w, n2_b, mln1_w, mln1_b, p_h, p_zh);

    dim3 gM1(DFF / 128, ROWS / 128);
    gemm_h<<<gM1, 256, GEMM_SMEM>>>(p_zh, p_W1h, mb1, nullptr, p_z1h, DFF, DD, 5);

    ln_kernel<<<ROWS, 256>>>(p_z1h, mln2_w, mln2_b, nullptr, p_z2h, DFF, 3);

    gemm_h<<<gP, 256, GEMM_SMEM>>>(p_z2h, p_W2h, mb2, p_h, out, DD, DFF, 3);
}